// round 11
// baseline (speedup 1.0000x reference)
#include <cuda_runtime.h>
#include <cuda_fp16.h>
#include <math.h>
#include <stddef.h>
#include <stdint.h>

// ---------------------------------------------------------------------------
// Problem constants
// ---------------------------------------------------------------------------
#define Bsz   4
#define Lsz   4096
#define Dsz   1024
#define WIDTH 3072
#define Msz   (Bsz * Lsz)      // 16384
#define NFFT  8192
#define FFT_THREADS 512
#define FFT_SMEM_BYTES ((2 * NFFT + NFFT / 2) * (int)sizeof(float2))  // 163840

#define KAUG  2048             // 2 * 1024 augmented-K for fp16x2 GEMM (A side)
#define KB    1024             // B stores hi segment only

// ---------------------------------------------------------------------------
// Helpers (baseline PTX only: sm_80-compatible — harness targets compute_100)
// ---------------------------------------------------------------------------
__device__ __forceinline__ uint32_t smem_u32(const void* p) {
    uint32_t a;
    asm("{ .reg .u64 t; cvta.to.shared.u64 t, %1; cvt.u32.u64 %0, t; }"
        : "=r"(a) : "l"(p));
    return a;
}

__device__ __forceinline__ void cpa16(uint32_t s, const void* g) {
    asm volatile("cp.async.cg.shared.global [%0], [%1], 16;" :: "r"(s), "l"(g));
}

__device__ __forceinline__ void ldsm4(uint32_t* r, uint32_t a) {
    asm volatile("ldmatrix.sync.aligned.m8n8.x4.shared.b16 {%0,%1,%2,%3}, [%4];"
        : "=r"(r[0]), "=r"(r[1]), "=r"(r[2]), "=r"(r[3]) : "r"(a));
}

__device__ __forceinline__ void mma_f16(float* c, const uint32_t* a, const uint32_t* b) {
    asm volatile(
        "mma.sync.aligned.m16n8k16.row.col.f32.f16.f16.f32 "
        "{%0,%1,%2,%3}, {%4,%5,%6,%7}, {%8,%9}, {%0,%1,%2,%3};"
        : "+f"(c[0]), "+f"(c[1]), "+f"(c[2]), "+f"(c[3])
        : "r"(a[0]), "r"(a[1]), "r"(a[2]), "r"(a[3]), "r"(b[0]), "r"(b[1]));
}

// ---------------------------------------------------------------------------
// Scratch (static device globals; no allocation allowed)
// ---------------------------------------------------------------------------
__device__ float  g_u  [(size_t)Msz * WIDTH];       // (B*L, 3D) fp32
__device__ float  g_x0T[(size_t)Bsz * Dsz * Lsz];   // (B, D, L)
__device__ float  g_vgT[(size_t)Bsz * Dsz * Lsz];   // (B, D, L)
__device__ float  g_kk [(size_t)Lsz * Dsz];         // flipped+decayed kernel
__device__ float2 g_Kf [(size_t)Dsz * 4097];        // per-channel spectrum
__device__ float  g_yT [(size_t)Bsz * Dsz * Lsz];   // (B, D, L)
__device__ __half g_A1 [(size_t)Msz * KAUG];        // [hi, lo] of x
__device__ __half g_Bt1[(size_t)WIDTH * KB];        // hi of W_in^T
__device__ __half g_A2 [(size_t)Msz * KAUG];        // [hi, lo] of y
__device__ __half g_Bt2[(size_t)Dsz * KB];          // hi of W_out^T

// ---------------------------------------------------------------------------
// fp16x2 mma.sync GEMM: C[M,N] = A'[M,2048] @ [Bhi,Bhi][N,2048]^T + bias
// BM=128, BN=128, BK=32, 256 thr, warp grid 2(m)x4(n), warp tile 64x32.
// 4-stage cp.async pipeline, XOR-swizzled smem, ldmatrix fragments.
// __launch_bounds__(256, 2): cap regs at 124 -> 2 CTAs/SM (16 warps) for
// latency hiding; smem 2 x 64KB = 128KB fits.
// ---------------------------------------------------------------------------
#define GS 4
#define STG 8192                       // bytes per operand stage (128 rows x 64B)
#define GM_SMEM (2 * GS * STG)         // 65536
#define NKI 64                         // 2048 / 32

__global__ __launch_bounds__(256, 2) void gemm_f16_kernel(
    const __half* __restrict__ A, const __half* __restrict__ Bw,
    const float* __restrict__ bias, float* __restrict__ C,
    const int M, const int N)
{
    extern __shared__ char gsm[];
    const uint32_t smA = smem_u32(gsm);
    const uint32_t smB = smA + GS * STG;

    const int tid = threadIdx.x;
    const int lid = tid & 31, wid = tid >> 5;
    const int wm = (wid & 1) * 64;      // warp m offset in tile
    const int wn = (wid >> 1) * 32;     // warp n offset in tile
    const int n0 = blockIdx.x * 128;
    const int m0 = blockIdx.y * 128;

    auto load_stage = [&](int buf, int k0) {
#pragma unroll
        for (int i = 0; i < 2; ++i) {
            int ch = tid + i * 256;               // 0..511
            int row = ch >> 2, c = ch & 3;
            uint32_t byte = (uint32_t)row * 64u + c * 16u;
            uint32_t sw = byte ^ ((row & 3) << 4);
            cpa16(smA + buf * STG + sw, A + (size_t)(m0 + row) * KAUG + k0 + c * 8);
        }
        const int kb = k0 & (KB - 1);
#pragma unroll
        for (int i = 0; i < 2; ++i) {
            int ch = tid + i * 256;
            int row = ch >> 2, c = ch & 3;
            uint32_t byte = (uint32_t)row * 64u + c * 16u;
            uint32_t sw = byte ^ ((row & 3) << 4);
            cpa16(smB + buf * STG + sw, Bw + (size_t)(n0 + row) * KB + kb + c * 8);
        }
        asm volatile("cp.async.commit_group;" ::: "memory");
    };

    float acc[4][4][4];
#pragma unroll
    for (int i = 0; i < 4; ++i)
#pragma unroll
        for (int j = 0; j < 4; ++j)
#pragma unroll
            for (int q = 0; q < 4; ++q) acc[i][j][q] = 0.f;

    for (int s = 0; s < GS - 1; ++s) load_stage(s, s * 32);

    for (int ks = 0; ks < NKI; ++ks) {
        if (ks + GS - 2 < NKI) asm volatile("cp.async.wait_group 2;" ::: "memory");
        else                   asm volatile("cp.async.wait_group 0;" ::: "memory");
        __syncthreads();
        const uint32_t sA = smA + (ks & (GS - 1)) * STG;
        const uint32_t sB = smB + (ks & (GS - 1)) * STG;
#pragma unroll
        for (int k2 = 0; k2 < 2; ++k2) {
            uint32_t af[4][4];
            uint32_t bfr[8];
#pragma unroll
            for (int tm = 0; tm < 4; ++tm) {
                int row = wm + tm * 16 + (lid & 15);
                uint32_t byte = (uint32_t)row * 64u + k2 * 32u + (lid >> 4) * 16u;
                ldsm4(af[tm], sA + (byte ^ ((row & 3) << 4)));
            }
#pragma unroll
            for (int tn2 = 0; tn2 < 2; ++tn2) {
                int row = wn + tn2 * 16 + ((lid >> 4) << 3) + (lid & 7);
                uint32_t byte = (uint32_t)row * 64u + k2 * 32u + ((lid >> 3) & 1) * 16u;
                ldsm4(&bfr[tn2 * 4], sB + (byte ^ ((row & 3) << 4)));
            }
#pragma unroll
            for (int tm = 0; tm < 4; ++tm)
#pragma unroll
                for (int tn = 0; tn < 4; ++tn)
                    mma_f16(acc[tm][tn], af[tm], &bfr[tn * 2]);
        }
        if (ks + GS - 1 < NKI) load_stage((ks + GS - 1) & (GS - 1), (ks + GS - 1) * 32);
    }

    // epilogue
#pragma unroll
    for (int tm = 0; tm < 4; ++tm) {
        int r0 = m0 + wm + tm * 16 + (lid >> 2);
#pragma unroll
        for (int tn = 0; tn < 4; ++tn) {
            int c = n0 + wn + tn * 8 + (lid & 3) * 2;
            float2 bv = *(const float2*)(bias + c);
            float2 v0 = make_float2(acc[tm][tn][0] + bv.x, acc[tm][tn][1] + bv.y);
            float2 v1 = make_float2(acc[tm][tn][2] + bv.x, acc[tm][tn][3] + bv.y);
            *(float2*)(C + (size_t)r0 * N + c) = v0;
            *(float2*)(C + (size_t)(r0 + 8) * N + c) = v1;
        }
    }
}

// ---------------------------------------------------------------------------
// Conversion kernels: fp32 -> fp16 [hi, lo] (A side) / hi (B side)
// ---------------------------------------------------------------------------
__device__ __forceinline__ void split_f16(float x, __half& hi, __half& lo) {
    hi = __float2half_rn(x);
    lo = __float2half_rn(x - __half2float(hi));
}

// x (M x 1024 fp32 row-major) -> A' (M x 2048 fp16)
__global__ __launch_bounds__(256) void convert_a_kernel(
    const float* __restrict__ X, __half* __restrict__ Aout)
{
    const size_t idx = (size_t)blockIdx.x * 256 + threadIdx.x;
    const size_t m = idx >> 10;
    const int k = (int)(idx & 1023);
    float v = X[idx];
    __half hi, lo; split_f16(v, hi, lo);
    __half* row = Aout + m * KAUG;
    row[k] = hi; row[Dsz + k] = lo;
}

// W (1024 x N fp32) -> Bhi (N x 1024 fp16), transposed
__global__ __launch_bounds__(1024) void convert_b_kernel(
    const float* __restrict__ W, __half* __restrict__ Bout, const int N)
{
    __shared__ float sm[32][33];
    const int n0 = blockIdx.x * 32;
    const int k0 = blockIdx.y * 32;
    const int tx = threadIdx.x & 31, ty = threadIdx.x >> 5;
    sm[ty][tx] = W[(size_t)(k0 + ty) * N + n0 + tx];
    __syncthreads();
    const int n = n0 + ty, k = k0 + tx;
    Bout[(size_t)n * KB + k] = __float2half_rn(sm[tx][ty]);
}

// yT (B, D, L fp32) -> A' (M=B*L x 2048 fp16), transposed per batch
__global__ __launch_bounds__(1024) void convert_y_kernel(
    const float* __restrict__ yT, __half* __restrict__ Aout)
{
    __shared__ float sm[32][33];
    const int t0 = blockIdx.x * 32;
    const int d0 = blockIdx.y * 32;
    const int b  = blockIdx.z;
    const int tx = threadIdx.x & 31, ty = threadIdx.x >> 5;
    sm[ty][tx] = yT[((size_t)(b * Dsz + d0 + ty)) * Lsz + t0 + tx];
    __syncthreads();
    const int t = t0 + ty, d = d0 + tx;
    __half hi, lo; split_f16(sm[tx][ty], hi, lo);
    __half* row = Aout + ((size_t)(b * Lsz + t)) * KAUG;
    row[d] = hi; row[Dsz + d] = lo;
}

// ---------------------------------------------------------------------------
// Short depthwise conv (k=3, causal) + gate; writes transposed (B, D, L).
// Each thread computes 4 consecutive t outputs: 6 shared taps serve 4 outputs
// per channel (2.7x fewer LDS) and stores fuse into one STG.128 per stream.
// ---------------------------------------------------------------------------
__global__ __launch_bounds__(256) void shortconv_kernel(
    const float* __restrict__ u, const float* __restrict__ sw,
    const float* __restrict__ sb, float* __restrict__ x0T,
    float* __restrict__ vgT)
{
    __shared__ float s[3][66 * 33];
    const int t0 = blockIdx.x * 64;
    const int d0 = blockIdx.y * 32;
    const int b  = blockIdx.z;
    const int tid = threadIdx.x;

#pragma unroll 1
    for (int c = 0; c < 3; ++c) {
        const float* up = u + (size_t)b * Lsz * WIDTH + c * Dsz + d0;
        for (int idx = tid; idx < 66 * 32; idx += 256) {
            int row = idx >> 5;
            int dc  = idx & 31;
            int t   = t0 - 2 + row;
            float v = (t >= 0) ? up[(size_t)t * WIDTH + dc] : 0.0f;
            s[c][row * 33 + dc] = v;
        }
    }
    __syncthreads();

    // 512 groups: dc in [0,32), tg in [0,16); each group = 4 outputs.
    for (int idx = tid; idx < 32 * 16; idx += 256) {
        const int dc = idx >> 4;
        const int tt = (idx & 15) * 4;
        const int d  = d0 + dc;

        const float* w0 = sw + (size_t)d * 3;
        const float* w1 = sw + (size_t)(Dsz + d) * 3;
        const float* w2 = sw + (size_t)(2 * Dsz + d) * 3;
        const float b0 = sb[d], b1 = sb[Dsz + d], b2 = sb[2 * Dsz + d];

        float a0[6], a1[6], a2[6];
#pragma unroll
        for (int r = 0; r < 6; ++r) {
            a0[r] = s[0][(tt + r) * 33 + dc];
            a1[r] = s[1][(tt + r) * 33 + dc];
            a2[r] = s[2][(tt + r) * 33 + dc];
        }

        float4 vx0, vvg;
        float* px = (float*)&vx0;
        float* pv = (float*)&vvg;
#pragma unroll
        for (int j = 0; j < 4; ++j) {
            float c0 = a0[j] * w0[0] + a0[j + 1] * w0[1] + a0[j + 2] * w0[2] + b0;
            float c1 = a1[j] * w1[0] + a1[j + 1] * w1[1] + a1[j + 2] * w1[2] + b1;
            float c2 = a2[j] * w2[0] + a2[j + 1] * w2[1] + a2[j + 2] * w2[2] + b2;
            px[j] = c0;
            pv[j] = c2 * c1;
        }
        const size_t o = ((size_t)(b * Dsz + d)) * Lsz + t0 + tt;
        *(float4*)(x0T + o) = vx0;
        *(float4*)(vgT + o) = vvg;
    }
}

// ---------------------------------------------------------------------------
// Filter MLP: one block per position i; writes flipped+decayed kernel
// ---------------------------------------------------------------------------
__global__ __launch_bounds__(256) void filter_kernel(
    const float* __restrict__ W1, const float* __restrict__ b1,
    const float* __restrict__ f1, const float* __restrict__ W2,
    const float* __restrict__ b2, const float* __restrict__ f2,
    const float* __restrict__ W3, const float* __restrict__ b3,
    float* __restrict__ kkout)
{
    __shared__ float h1[64], h2[64];
    const int i = blockIdx.x;
    const int tid = threadIdx.x;
    const float tn = (float)i * (1.0f / 4095.0f);
    const float phase = 1e-4f * (6.2831853071795864769f * (float)i / 4096.0f);

    if (tid < 64) {
        float sp, cp; sincosf(phase, &sp, &cp);
        float a = tn * W1[tid] + cp * W1[64 + tid] - sp * W1[128 + tid] + b1[tid];
        h1[tid] = sinf(a * f1[tid]);
    }
    __syncthreads();
    if (tid < 64) {
        float a = b2[tid];
#pragma unroll 8
        for (int c = 0; c < 64; ++c) a += h1[c] * W2[c * 64 + tid];
        h2[tid] = sinf(a * f2[tid]);
    }
    __syncthreads();

    const float dmax = -15.350567286626971f;  // log(0.01)/0.3
    const float dmin = -3.0701134573253943f;  // log(0.01)/1.5
    const int row = Lsz - 1 - i;
    for (int d = tid; d < Dsz; d += 256) {
        float a = b3[d];
#pragma unroll 8
        for (int c = 0; c < 64; ++c) a += h2[c] * W3[c * Dsz + d];
        float delta = fabsf(dmax + (dmin - dmax) * ((float)d * (1.0f / 1023.0f)));
        kkout[(size_t)row * Dsz + d] = a * expf(-tn * delta);
    }
}

// ---------------------------------------------------------------------------
// Stockham FFT, N=8192: 6 radix-4 passes + 1 trivial radix-2.
// PADDED=true: input upper half (indices 4096..8191) is implicitly zero and
// must NOT have been written; pass 0 then reads only the lower half.
// ---------------------------------------------------------------------------
template<bool PADDED>
__device__ __forceinline__ float2* fft8192(float2* buf0, float2* buf1,
                                           const float2* __restrict__ tw,
                                           bool inverse)
{
    float2* src = buf0;
    float2* dst = buf1;
#pragma unroll 1
    for (int p = 0; p < 6; ++p) {
        const int s = 1 << (2 * p);
        __syncthreads();
        if (PADDED && p == 0) {
            // B = D = 0: half the loads, q=0, m=i.
#pragma unroll
            for (int ii = 0; ii < NFFT / 4 / FFT_THREADS; ++ii) {
                const int i = threadIdx.x + ii * FFT_THREADS;
                float2 A = src[i];
                float2 C = src[i + 2048];
                float2 w1 = tw[i];
                float2 w2 = tw[2 * i];
                const float s1y = inverse ? -w1.y : w1.y;
                const float s2y = inverse ? -w2.y : w2.y;
                float2 jd = inverse ? make_float2(-C.y, C.x)
                                    : make_float2(C.y, -C.x);
                float2 t0 = make_float2(A.x + C.x, A.y + C.y);
                float2 t2 = make_float2(A.x - C.x, A.y - C.y);
                float2 t1 = make_float2(A.x + jd.x, A.y + jd.y);
                float2 t3 = make_float2(A.x - jd.x, A.y - jd.y);
                float2 o1 = make_float2(t1.x * w1.x - t1.y * s1y, t1.x * s1y + t1.y * w1.x);
                float2 o2 = make_float2(t2.x * w2.x - t2.y * s2y, t2.x * s2y + t2.y * w2.x);
                const float w3x = w1.x * w2.x - s1y * s2y;
                const float w3y = w1.x * s2y + s1y * w2.x;
                float2 o3 = make_float2(t3.x * w3x - t3.y * w3y, t3.x * w3y + t3.y * w3x);
                const int base = 4 * i;
                dst[base]     = t0;
                dst[base + 1] = o1;
                dst[base + 2] = o2;
                dst[base + 3] = o3;
            }
        } else {
#pragma unroll
            for (int ii = 0; ii < NFFT / 4 / FFT_THREADS; ++ii) {
                const int i = threadIdx.x + ii * FFT_THREADS;
                const int q = i & (s - 1);
                const int m = i - q;
                float2 A = src[i];
                float2 C = src[i + 2048];
                float2 B = src[i + 4096];
                float2 D = src[i + 6144];
                float2 w1 = tw[m];
                float2 w2 = tw[2 * m];
                const float s1y = inverse ? -w1.y : w1.y;
                const float s2y = inverse ? -w2.y : w2.y;
                float2 sAB = make_float2(A.x + B.x, A.y + B.y);
                float2 dAB = make_float2(A.x - B.x, A.y - B.y);
                float2 sCD = make_float2(C.x + D.x, C.y + D.y);
                float2 dCD = make_float2(C.x - D.x, C.y - D.y);
                float2 jd = inverse ? make_float2(-dCD.y, dCD.x)
                                    : make_float2(dCD.y, -dCD.x);
                float2 t0 = make_float2(sAB.x + sCD.x, sAB.y + sCD.y);
                float2 t2 = make_float2(sAB.x - sCD.x, sAB.y - sCD.y);
                float2 t1 = make_float2(dAB.x + jd.x, dAB.y + jd.y);
                float2 t3 = make_float2(dAB.x - jd.x, dAB.y - jd.y);
                float2 o1 = make_float2(t1.x * w1.x - t1.y * s1y, t1.x * s1y + t1.y * w1.x);
                float2 o2 = make_float2(t2.x * w2.x - t2.y * s2y, t2.x * s2y + t2.y * w2.x);
                const float w3x = w1.x * w2.x - s1y * s2y;
                const float w3y = w1.x * s2y + s1y * w2.x;
                float2 o3 = make_float2(t3.x * w3x - t3.y * w3y, t3.x * w3y + t3.y * w3x);
                const int base = 4 * m + q;
                dst[base]         = t0;
                dst[base + s]     = o1;
                dst[base + 2 * s] = o2;
                dst[base + 3 * s] = o3;
            }
        }
        float2* tmp = src; src = dst; dst = tmp;
    }
    // final radix-2 stage (s=4096): twiddle index is 0 -> w = 1
    __syncthreads();
#pragma unroll
    for (int ii = 0; ii < NFFT / 2 / FFT_THREADS; ++ii) {
        const int t = threadIdx.x + ii * FFT_THREADS;
        float2 a = src[t];
        float2 b = src[t + 4096];
        dst[t]        = make_float2(a.x + b.x, a.y + b.y);
        dst[t + 4096] = make_float2(a.x - b.x, a.y - b.y);
    }
    __syncthreads();
    return dst;
}

__device__ __forceinline__ float2 cmulf(float2 a, float2 b) {
    return make_float2(a.x * b.x - a.y * b.y, a.x * b.y + a.y * b.x);
}

__global__ __launch_bounds__(FFT_THREADS) void kfft_kernel(
    const float* __restrict__ kk, float2* __restrict__ Kf)
{
    extern __shared__ float2 sm[];
    float2* bufA = sm;
    float2* bufB = sm + NFFT;
    float2* tw   = sm + 2 * NFFT;
    const int d0 = blockIdx.x * 2;

    for (int j = threadIdx.x; j < NFFT / 2; j += FFT_THREADS) {
        float sn, cs;
        sincosf((float)j * (-6.2831853071795864769f / (float)NFFT), &sn, &cs);
        tw[j] = make_float2(cs, sn);
        bufA[j] = make_float2(kk[(size_t)j * Dsz + d0], kk[(size_t)j * Dsz + d0 + 1]);
    }
    float2* Z = fft8192<true>(bufA, bufB, tw, false);
    float2* Ka = Kf + (size_t)d0 * 4097;
    float2* Kb = Ka + 4097;
    for (int k = threadIdx.x; k <= NFFT / 2; k += FFT_THREADS) {
        float2 z  = Z[k];
        float2 zc = Z[(NFFT - k) & (NFFT - 1)];
        Ka[k] = make_float2(0.5f * (z.x + zc.x), 0.5f * (z.y - zc.y));
        Kb[k] = make_float2(0.5f * (z.y + zc.y), 0.5f * (zc.x - z.x));
    }
}

__global__ __launch_bounds__(FFT_THREADS) void vfft_kernel(
    const float* __restrict__ vgT, const float* __restrict__ x0T,
    const float2* __restrict__ Kf, const float* __restrict__ fbias,
    float* __restrict__ yT)
{
    extern __shared__ float2 sm[];
    float2* bufA = sm;
    float2* bufB = sm + NFFT;
    float2* tw   = sm + 2 * NFFT;
    const int pair = blockIdx.x;
    const int b    = blockIdx.y;
    const int d0   = pair * 2;
    const float* v0 = vgT + ((size_t)(b * Dsz + d0)) * Lsz;
    const float* v1 = v0 + Lsz;

    for (int j = threadIdx.x; j < NFFT / 2; j += FFT_THREADS) {
        float sn, cs;
        sincosf((float)j * (-6.2831853071795864769f / (float)NFFT), &sn, &cs);
        tw[j] = make_float2(cs, sn);
        bufA[j] = make_float2(v0[j], v1[j]);
    }
    float2* Z = fft8192<true>(bufA, bufB, tw, false);   // == bufB
    float2* W = (Z == bufA) ? bufB : bufA;              // == bufA

    const float2* Ka = Kf + (size_t)d0 * 4097;
    const float2* Kb = Ka + 4097;
    for (int k = threadIdx.x; k <= NFFT / 2; k += FFT_THREADS) {
        float2 z  = Z[k];
        float2 zc = Z[(NFFT - k) & (NFFT - 1)];
        float2 Ak = make_float2(0.5f * (z.x + zc.x), 0.5f * (z.y - zc.y));
        float2 Bk = make_float2(0.5f * (z.y + zc.y), 0.5f * (zc.x - z.x));
        float2 Ya = cmulf(Ak, Ka[k]);
        float2 Yb = cmulf(Bk, Kb[k]);
        W[k] = make_float2(Ya.x - Yb.y, Ya.y + Yb.x);
        if (k != 0 && k != NFFT / 2)
            W[NFFT - k] = make_float2(Ya.x + Yb.y, Yb.x - Ya.y);
    }
    float2* res = fft8192<false>(W, Z, tw, true);       // unnormalized inverse

    const float invN = 1.0f / (float)NFFT;
    const float fb0 = fbias[d0], fb1 = fbias[d0 + 1];
    const float* x0a = x0T + ((size_t)(b * Dsz + d0)) * Lsz;
    const float* x0b = x0a + Lsz;
    float* ya = yT + ((size_t)(b * Dsz + d0)) * Lsz;
    float* yb = ya + Lsz;
    for (int t = threadIdx.x; t < Lsz; t += FFT_THREADS) {
        float2 w = res[t];
        ya[t] = (w.x * invN + fb0) * x0a[t];
        yb[t] = (w.y * invN + fb1) * x0b[t];
    }
}

// ---------------------------------------------------------------------------
// Launch
// ---------------------------------------------------------------------------
extern "C" void kernel_launch(void* const* d_in, const int* in_sizes, int n_in,
                              void* d_out, int out_size)
{
    const float* x       = (const float*)d_in[0];
    const float* W_in    = (const float*)d_in[1];
    const float* b_in    = (const float*)d_in[2];
    const float* short_w = (const float*)d_in[3];
    const float* short_b = (const float*)d_in[4];
    const float* W1      = (const float*)d_in[5];
    const float* b1      = (const float*)d_in[6];
    const float* f1      = (const float*)d_in[7];
    const float* W2      = (const float*)d_in[8];
    const float* b2      = (const float*)d_in[9];
    const float* f2      = (const float*)d_in[10];
    const float* W3      = (const float*)d_in[11];
    const float* b3      = (const float*)d_in[12];
    const float* fbias   = (const float*)d_in[13];
    const float* W_out   = (const float*)d_in[14];
    const float* b_out   = (const float*)d_in[15];
    float* out = (float*)d_out;

    float *p_u, *p_x0, *p_vg, *p_kk, *p_y;
    float2* p_Kf;
    __half *p_A1, *p_Bt1, *p_A2, *p_Bt2;
    cudaGetSymbolAddress((void**)&p_u,   g_u);
    cudaGetSymbolAddress((void**)&p_x0,  g_x0T);
    cudaGetSymbolAddress((void**)&p_vg,  g_vgT);
    cudaGetSymbolAddress((void**)&p_kk,  g_kk);
    cudaGetSymbolAddress((void**)&p_Kf,  g_Kf);
    cudaGetSymbolAddress((void**)&p_y,   g_yT);
    cudaGetSymbolAddress((void**)&p_A1,  g_A1);
    cudaGetSymbolAddress((void**)&p_Bt1, g_Bt1);
    cudaGetSymbolAddress((void**)&p_A2,  g_A2);
    cudaGetSymbolAddress((void**)&p_Bt2, g_Bt2);

    cudaFuncSetAttribute(kfft_kernel, cudaFuncAttributeMaxDynamicSharedMemorySize,
                         FFT_SMEM_BYTES);
    cudaFuncSetAttribute(vfft_kernel, cudaFuncAttributeMaxDynamicSharedMemorySize,
                         FFT_SMEM_BYTES);
    cudaFuncSetAttribute(gemm_f16_kernel, cudaFuncAttributeMaxDynamicSharedMemorySize,
                         GM_SMEM);

    // 1) operand conversion for GEMM1
    convert_a_kernel<<<(size_t)Msz * Dsz / 256, 256>>>(x, p_A1);
    convert_b_kernel<<<dim3(WIDTH / 32, Dsz / 32), 1024>>>(W_in, p_Bt1, WIDTH);

    // 2) u = x @ W_in + b_in  (fp16x2 mma.sync)
    gemm_f16_kernel<<<dim3(WIDTH / 128, Msz / 128), 256, GM_SMEM>>>(
        p_A1, p_Bt1, b_in, p_u, Msz, WIDTH);

    // 3) short conv + gate -> x0T, vgT (transposed B,D,L)
    shortconv_kernel<<<dim3(Lsz / 64, Dsz / 32, Bsz), 256>>>(
        p_u, short_w, short_b, p_x0, p_vg);

    // 4) implicit filter (flipped + decayed)
    filter_kernel<<<Lsz, 256>>>(W1, b1, f1, W2, b2, f2, W3, b3, p_kk);

    // 5) filter spectra
    kfft_kernel<<<Dsz / 2, FFT_THREADS, FFT_SMEM_BYTES>>>(p_kk, p_Kf);

    // 6) FFT conv + bias + x0 gate
    vfft_kernel<<<dim3(Dsz / 2, Bsz), FFT_THREADS, FFT_SMEM_BYTES>>>(
        p_vg, p_x0, p_Kf, fbias, p_y);

    // 7) operand conversion for GEMM2
    convert_b_kernel<<<dim3(Dsz / 32, Dsz / 32), 1024>>>(W_out, p_Bt2, Dsz);
    convert_y_kernel<<<dim3(Lsz / 32, Dsz / 32, Bsz), 1024>>>(p_y, p_A2);

    // 8) out = y @ W_out + b_out  (fp16x2 mma.sync)
    gemm_f16_kernel<<<dim3(Dsz / 128, Msz / 128), 256, GM_SMEM>>>(
        p_A2, p_Bt2, b_out, out, Msz, Dsz);
}

// round 12
// speedup vs baseline: 1.0331x; 1.0331x over previous
#include <cuda_runtime.h>
#include <cuda_fp16.h>
#include <math.h>
#include <stddef.h>
#include <stdint.h>

// ---------------------------------------------------------------------------
// Problem constants
// ---------------------------------------------------------------------------
#define Bsz   4
#define Lsz   4096
#define Dsz   1024
#define WIDTH 3072
#define Msz   (Bsz * Lsz)      // 16384
#define NFFT  8192
#define FFT_THREADS 512
#define FFT_SMEM_BYTES ((2 * NFFT + NFFT / 2) * (int)sizeof(float2))  // 163840

#define KAUG  2048             // 2 * 1024 augmented-K for fp16x2 GEMM (A side)
#define KB    1024             // B stores hi segment only

// ---------------------------------------------------------------------------
// Helpers (baseline PTX only: sm_80-compatible — harness targets compute_100)
// ---------------------------------------------------------------------------
__device__ __forceinline__ uint32_t smem_u32(const void* p) {
    uint32_t a;
    asm("{ .reg .u64 t; cvta.to.shared.u64 t, %1; cvt.u32.u64 %0, t; }"
        : "=r"(a) : "l"(p));
    return a;
}

__device__ __forceinline__ void cpa16(uint32_t s, const void* g) {
    asm volatile("cp.async.cg.shared.global [%0], [%1], 16;" :: "r"(s), "l"(g));
}

__device__ __forceinline__ void ldsm4(uint32_t* r, uint32_t a) {
    asm volatile("ldmatrix.sync.aligned.m8n8.x4.shared.b16 {%0,%1,%2,%3}, [%4];"
        : "=r"(r[0]), "=r"(r[1]), "=r"(r[2]), "=r"(r[3]) : "r"(a));
}

__device__ __forceinline__ void mma_f16(float* c, const uint32_t* a, const uint32_t* b) {
    asm volatile(
        "mma.sync.aligned.m16n8k16.row.col.f32.f16.f16.f32 "
        "{%0,%1,%2,%3}, {%4,%5,%6,%7}, {%8,%9}, {%0,%1,%2,%3};"
        : "+f"(c[0]), "+f"(c[1]), "+f"(c[2]), "+f"(c[3])
        : "r"(a[0]), "r"(a[1]), "r"(a[2]), "r"(a[3]), "r"(b[0]), "r"(b[1]));
}

// ---------------------------------------------------------------------------
// Scratch (static device globals; no allocation allowed)
// ---------------------------------------------------------------------------
__device__ __half g_u  [(size_t)Msz * WIDTH];       // (B*L, 3D) fp16 intermediate
__device__ float  g_x0T[(size_t)Bsz * Dsz * Lsz];   // (B, D, L)
__device__ float  g_vgT[(size_t)Bsz * Dsz * Lsz];   // (B, D, L)
__device__ float  g_kk [(size_t)Lsz * Dsz];         // flipped+decayed kernel
__device__ float2 g_Kf [(size_t)Dsz * 4097];        // per-channel spectrum
__device__ float  g_yT [(size_t)Bsz * Dsz * Lsz];   // (B, D, L)
__device__ __half g_A1 [(size_t)Msz * KAUG];        // [hi, lo] of x
__device__ __half g_Bt1[(size_t)WIDTH * KB];        // hi of W_in^T
__device__ __half g_A2 [(size_t)Msz * KAUG];        // [hi, lo] of y
__device__ __half g_Bt2[(size_t)Dsz * KB];          // hi of W_out^T

// ---------------------------------------------------------------------------
// fp16x2 mma.sync GEMM: C[M,N] = A'[M,2048] @ [Bhi,Bhi][N,2048]^T + bias
// BM=128, BN=128, BK=32, 256 thr, warp grid 2(m)x4(n), warp tile 64x32.
// 4-stage cp.async pipeline, XOR-swizzled smem, ldmatrix fragments.
// OutT = __half (intermediate u) or float (final out).
// ---------------------------------------------------------------------------
#define GS 4
#define STG 8192                       // bytes per operand stage (128 rows x 64B)
#define GM_SMEM (2 * GS * STG)         // 65536
#define NKI 64                         // 2048 / 32

template<typename OutT>
__global__ __launch_bounds__(256) void gemm_f16_kernel(
    const __half* __restrict__ A, const __half* __restrict__ Bw,
    const float* __restrict__ bias, OutT* __restrict__ C,
    const int M, const int N)
{
    extern __shared__ char gsm[];
    const uint32_t smA = smem_u32(gsm);
    const uint32_t smB = smA + GS * STG;

    const int tid = threadIdx.x;
    const int lid = tid & 31, wid = tid >> 5;
    const int wm = (wid & 1) * 64;      // warp m offset in tile
    const int wn = (wid >> 1) * 32;     // warp n offset in tile
    const int n0 = blockIdx.x * 128;
    const int m0 = blockIdx.y * 128;

    auto load_stage = [&](int buf, int k0) {
#pragma unroll
        for (int i = 0; i < 2; ++i) {
            int ch = tid + i * 256;               // 0..511
            int row = ch >> 2, c = ch & 3;
            uint32_t byte = (uint32_t)row * 64u + c * 16u;
            uint32_t sw = byte ^ ((row & 3) << 4);
            cpa16(smA + buf * STG + sw, A + (size_t)(m0 + row) * KAUG + k0 + c * 8);
        }
        const int kb = k0 & (KB - 1);
#pragma unroll
        for (int i = 0; i < 2; ++i) {
            int ch = tid + i * 256;
            int row = ch >> 2, c = ch & 3;
            uint32_t byte = (uint32_t)row * 64u + c * 16u;
            uint32_t sw = byte ^ ((row & 3) << 4);
            cpa16(smB + buf * STG + sw, Bw + (size_t)(n0 + row) * KB + kb + c * 8);
        }
        asm volatile("cp.async.commit_group;" ::: "memory");
    };

    float acc[4][4][4];
#pragma unroll
    for (int i = 0; i < 4; ++i)
#pragma unroll
        for (int j = 0; j < 4; ++j)
#pragma unroll
            for (int q = 0; q < 4; ++q) acc[i][j][q] = 0.f;

    for (int s = 0; s < GS - 1; ++s) load_stage(s, s * 32);

    for (int ks = 0; ks < NKI; ++ks) {
        if (ks + GS - 2 < NKI) asm volatile("cp.async.wait_group 2;" ::: "memory");
        else                   asm volatile("cp.async.wait_group 0;" ::: "memory");
        __syncthreads();
        const uint32_t sA = smA + (ks & (GS - 1)) * STG;
        const uint32_t sB = smB + (ks & (GS - 1)) * STG;
#pragma unroll
        for (int k2 = 0; k2 < 2; ++k2) {
            uint32_t af[4][4];
            uint32_t bfr[8];
#pragma unroll
            for (int tm = 0; tm < 4; ++tm) {
                int row = wm + tm * 16 + (lid & 15);
                uint32_t byte = (uint32_t)row * 64u + k2 * 32u + (lid >> 4) * 16u;
                ldsm4(af[tm], sA + (byte ^ ((row & 3) << 4)));
            }
#pragma unroll
            for (int tn2 = 0; tn2 < 2; ++tn2) {
                int row = wn + tn2 * 16 + ((lid >> 4) << 3) + (lid & 7);
                uint32_t byte = (uint32_t)row * 64u + k2 * 32u + ((lid >> 3) & 1) * 16u;
                ldsm4(&bfr[tn2 * 4], sB + (byte ^ ((row & 3) << 4)));
            }
#pragma unroll
            for (int tm = 0; tm < 4; ++tm)
#pragma unroll
                for (int tn = 0; tn < 4; ++tn)
                    mma_f16(acc[tm][tn], af[tm], &bfr[tn * 2]);
        }
        if (ks + GS - 1 < NKI) load_stage((ks + GS - 1) & (GS - 1), (ks + GS - 1) * 32);
    }

    // epilogue
#pragma unroll
    for (int tm = 0; tm < 4; ++tm) {
        int r0 = m0 + wm + tm * 16 + (lid >> 2);
#pragma unroll
        for (int tn = 0; tn < 4; ++tn) {
            int c = n0 + wn + tn * 8 + (lid & 3) * 2;
            float2 bv = *(const float2*)(bias + c);
            float v00 = acc[tm][tn][0] + bv.x, v01 = acc[tm][tn][1] + bv.y;
            float v10 = acc[tm][tn][2] + bv.x, v11 = acc[tm][tn][3] + bv.y;
            if (sizeof(OutT) == 2) {
                __half2* p0 = (__half2*)((__half*)C + (size_t)r0 * N + c);
                __half2* p1 = (__half2*)((__half*)C + (size_t)(r0 + 8) * N + c);
                *p0 = __floats2half2_rn(v00, v01);
                *p1 = __floats2half2_rn(v10, v11);
            } else {
                *(float2*)((float*)C + (size_t)r0 * N + c) = make_float2(v00, v01);
                *(float2*)((float*)C + (size_t)(r0 + 8) * N + c) = make_float2(v10, v11);
            }
        }
    }
}

// ---------------------------------------------------------------------------
// Conversion kernels: fp32 -> fp16 [hi, lo] (A side) / hi (B side)
// ---------------------------------------------------------------------------
__device__ __forceinline__ void split_f16(float x, __half& hi, __half& lo) {
    hi = __float2half_rn(x);
    lo = __float2half_rn(x - __half2float(hi));
}

// x (M x 1024 fp32 row-major) -> A' (M x 2048 fp16)
__global__ __launch_bounds__(256) void convert_a_kernel(
    const float* __restrict__ X, __half* __restrict__ Aout)
{
    const size_t idx = (size_t)blockIdx.x * 256 + threadIdx.x;
    const size_t m = idx >> 10;
    const int k = (int)(idx & 1023);
    float v = X[idx];
    __half hi, lo; split_f16(v, hi, lo);
    __half* row = Aout + m * KAUG;
    row[k] = hi; row[Dsz + k] = lo;
}

// W (1024 x N fp32) -> Bhi (N x 1024 fp16), transposed
__global__ __launch_bounds__(1024) void convert_b_kernel(
    const float* __restrict__ W, __half* __restrict__ Bout, const int N)
{
    __shared__ float sm[32][33];
    const int n0 = blockIdx.x * 32;
    const int k0 = blockIdx.y * 32;
    const int tx = threadIdx.x & 31, ty = threadIdx.x >> 5;
    sm[ty][tx] = W[(size_t)(k0 + ty) * N + n0 + tx];
    __syncthreads();
    const int n = n0 + ty, k = k0 + tx;
    Bout[(size_t)n * KB + k] = __float2half_rn(sm[tx][ty]);
}

// yT (B, D, L fp32) -> A' (M=B*L x 2048 fp16), transposed per batch
__global__ __launch_bounds__(1024) void convert_y_kernel(
    const float* __restrict__ yT, __half* __restrict__ Aout)
{
    __shared__ float sm[32][33];
    const int t0 = blockIdx.x * 32;
    const int d0 = blockIdx.y * 32;
    const int b  = blockIdx.z;
    const int tx = threadIdx.x & 31, ty = threadIdx.x >> 5;
    sm[ty][tx] = yT[((size_t)(b * Dsz + d0 + ty)) * Lsz + t0 + tx];
    __syncthreads();
    const int t = t0 + ty, d = d0 + tx;
    __half hi, lo; split_f16(sm[tx][ty], hi, lo);
    __half* row = Aout + ((size_t)(b * Lsz + t)) * KAUG;
    row[d] = hi; row[Dsz + d] = lo;
}

// ---------------------------------------------------------------------------
// Short depthwise conv (k=3, causal) + gate; writes transposed (B, D, L).
// (R9 mapping — measured fastest; input now fp16, converted on smem fill.)
// ---------------------------------------------------------------------------
__global__ __launch_bounds__(256) void shortconv_kernel(
    const __half* __restrict__ u, const float* __restrict__ sw,
    const float* __restrict__ sb, float* __restrict__ x0T,
    float* __restrict__ vgT)
{
    __shared__ float s[3][66 * 33];
    const int t0 = blockIdx.x * 64;
    const int d0 = blockIdx.y * 32;
    const int b  = blockIdx.z;
    const int tid = threadIdx.x;

#pragma unroll 1
    for (int c = 0; c < 3; ++c) {
        const __half* up = u + (size_t)b * Lsz * WIDTH + c * Dsz + d0;
        for (int idx = tid; idx < 66 * 32; idx += 256) {
            int row = idx >> 5;
            int dc  = idx & 31;
            int t   = t0 - 2 + row;
            float v = (t >= 0) ? __half2float(up[(size_t)t * WIDTH + dc]) : 0.0f;
            s[c][row * 33 + dc] = v;
        }
    }
    __syncthreads();

    for (int idx = tid; idx < 64 * 32; idx += 256) {
        int dc = idx >> 6;
        int tt = idx & 63;
        int d  = d0 + dc;
        int t  = t0 + tt;
        const float* w0 = sw + (size_t)d * 3;
        const float* w1 = sw + (size_t)(Dsz + d) * 3;
        const float* w2 = sw + (size_t)(2 * Dsz + d) * 3;
        float c0 = s[0][tt * 33 + dc] * w0[0] + s[0][(tt + 1) * 33 + dc] * w0[1]
                 + s[0][(tt + 2) * 33 + dc] * w0[2] + sb[d];
        float c1 = s[1][tt * 33 + dc] * w1[0] + s[1][(tt + 1) * 33 + dc] * w1[1]
                 + s[1][(tt + 2) * 33 + dc] * w1[2] + sb[Dsz + d];
        float c2 = s[2][tt * 33 + dc] * w2[0] + s[2][(tt + 1) * 33 + dc] * w2[1]
                 + s[2][(tt + 2) * 33 + dc] * w2[2] + sb[2 * Dsz + d];
        size_t o = ((size_t)(b * Dsz + d)) * Lsz + t;
        x0T[o] = c0;
        vgT[o] = c2 * c1;
    }
}

// ---------------------------------------------------------------------------
// Filter MLP: one block per position i; writes flipped+decayed kernel
// ---------------------------------------------------------------------------
__global__ __launch_bounds__(256) void filter_kernel(
    const float* __restrict__ W1, const float* __restrict__ b1,
    const float* __restrict__ f1, const float* __restrict__ W2,
    const float* __restrict__ b2, const float* __restrict__ f2,
    const float* __restrict__ W3, const float* __restrict__ b3,
    float* __restrict__ kkout)
{
    __shared__ float h1[64], h2[64];
    const int i = blockIdx.x;
    const int tid = threadIdx.x;
    const float tn = (float)i * (1.0f / 4095.0f);
    const float phase = 1e-4f * (6.2831853071795864769f * (float)i / 4096.0f);

    if (tid < 64) {
        float sp, cp; sincosf(phase, &sp, &cp);
        float a = tn * W1[tid] + cp * W1[64 + tid] - sp * W1[128 + tid] + b1[tid];
        h1[tid] = sinf(a * f1[tid]);
    }
    __syncthreads();
    if (tid < 64) {
        float a = b2[tid];
#pragma unroll 8
        for (int c = 0; c < 64; ++c) a += h1[c] * W2[c * 64 + tid];
        h2[tid] = sinf(a * f2[tid]);
    }
    __syncthreads();

    const float dmax = -15.350567286626971f;  // log(0.01)/0.3
    const float dmin = -3.0701134573253943f;  // log(0.01)/1.5
    const int row = Lsz - 1 - i;
    for (int d = tid; d < Dsz; d += 256) {
        float a = b3[d];
#pragma unroll 8
        for (int c = 0; c < 64; ++c) a += h2[c] * W3[c * Dsz + d];
        float delta = fabsf(dmax + (dmin - dmax) * ((float)d * (1.0f / 1023.0f)));
        kkout[(size_t)row * Dsz + d] = a * expf(-tn * delta);
    }
}

// ---------------------------------------------------------------------------
// Stockham FFT, N=8192: 6 radix-4 passes + 1 trivial radix-2.
// PADDED=true: input upper half (indices 4096..8191) is implicitly zero and
// must NOT have been written; pass 0 then reads only the lower half.
// ---------------------------------------------------------------------------
template<bool PADDED>
__device__ __forceinline__ float2* fft8192(float2* buf0, float2* buf1,
                                           const float2* __restrict__ tw,
                                           bool inverse)
{
    float2* src = buf0;
    float2* dst = buf1;
#pragma unroll 1
    for (int p = 0; p < 6; ++p) {
        const int s = 1 << (2 * p);
        __syncthreads();
        if (PADDED && p == 0) {
            // B = D = 0: half the loads, q=0, m=i.
#pragma unroll
            for (int ii = 0; ii < NFFT / 4 / FFT_THREADS; ++ii) {
                const int i = threadIdx.x + ii * FFT_THREADS;
                float2 A = src[i];
                float2 C = src[i + 2048];
                float2 w1 = tw[i];
                float2 w2 = tw[2 * i];
                const float s1y = inverse ? -w1.y : w1.y;
                const float s2y = inverse ? -w2.y : w2.y;
                float2 jd = inverse ? make_float2(-C.y, C.x)
                                    : make_float2(C.y, -C.x);
                float2 t0 = make_float2(A.x + C.x, A.y + C.y);
                float2 t2 = make_float2(A.x - C.x, A.y - C.y);
                float2 t1 = make_float2(A.x + jd.x, A.y + jd.y);
                float2 t3 = make_float2(A.x - jd.x, A.y - jd.y);
                float2 o1 = make_float2(t1.x * w1.x - t1.y * s1y, t1.x * s1y + t1.y * w1.x);
                float2 o2 = make_float2(t2.x * w2.x - t2.y * s2y, t2.x * s2y + t2.y * w2.x);
                const float w3x = w1.x * w2.x - s1y * s2y;
                const float w3y = w1.x * s2y + s1y * w2.x;
                float2 o3 = make_float2(t3.x * w3x - t3.y * w3y, t3.x * w3y + t3.y * w3x);
                const int base = 4 * i;
                dst[base]     = t0;
                dst[base + 1] = o1;
                dst[base + 2] = o2;
                dst[base + 3] = o3;
            }
        } else {
#pragma unroll
            for (int ii = 0; ii < NFFT / 4 / FFT_THREADS; ++ii) {
                const int i = threadIdx.x + ii * FFT_THREADS;
                const int q = i & (s - 1);
                const int m = i - q;
                float2 A = src[i];
                float2 C = src[i + 2048];
                float2 B = src[i + 4096];
                float2 D = src[i + 6144];
                float2 w1 = tw[m];
                float2 w2 = tw[2 * m];
                const float s1y = inverse ? -w1.y : w1.y;
                const float s2y = inverse ? -w2.y : w2.y;
                float2 sAB = make_float2(A.x + B.x, A.y + B.y);
                float2 dAB = make_float2(A.x - B.x, A.y - B.y);
                float2 sCD = make_float2(C.x + D.x, C.y + D.y);
                float2 dCD = make_float2(C.x - D.x, C.y - D.y);
                float2 jd = inverse ? make_float2(-dCD.y, dCD.x)
                                    : make_float2(dCD.y, -dCD.x);
                float2 t0 = make_float2(sAB.x + sCD.x, sAB.y + sCD.y);
                float2 t2 = make_float2(sAB.x - sCD.x, sAB.y - sCD.y);
                float2 t1 = make_float2(dAB.x + jd.x, dAB.y + jd.y);
                float2 t3 = make_float2(dAB.x - jd.x, dAB.y - jd.y);
                float2 o1 = make_float2(t1.x * w1.x - t1.y * s1y, t1.x * s1y + t1.y * w1.x);
                float2 o2 = make_float2(t2.x * w2.x - t2.y * s2y, t2.x * s2y + t2.y * w2.x);
                const float w3x = w1.x * w2.x - s1y * s2y;
                const float w3y = w1.x * s2y + s1y * w2.x;
                float2 o3 = make_float2(t3.x * w3x - t3.y * w3y, t3.x * w3y + t3.y * w3x);
                const int base = 4 * m + q;
                dst[base]         = t0;
                dst[base + s]     = o1;
                dst[base + 2 * s] = o2;
                dst[base + 3 * s] = o3;
            }
        }
        float2* tmp = src; src = dst; dst = tmp;
    }
    // final radix-2 stage (s=4096): twiddle index is 0 -> w = 1
    __syncthreads();
#pragma unroll
    for (int ii = 0; ii < NFFT / 2 / FFT_THREADS; ++ii) {
        const int t = threadIdx.x + ii * FFT_THREADS;
        float2 a = src[t];
        float2 b = src[t + 4096];
        dst[t]        = make_float2(a.x + b.x, a.y + b.y);
        dst[t + 4096] = make_float2(a.x - b.x, a.y - b.y);
    }
    __syncthreads();
    return dst;
}

__device__ __forceinline__ float2 cmulf(float2 a, float2 b) {
    return make_float2(a.x * b.x - a.y * b.y, a.x * b.y + a.y * b.x);
}

__global__ __launch_bounds__(FFT_THREADS) void kfft_kernel(
    const float* __restrict__ kk, float2* __restrict__ Kf)
{
    extern __shared__ float2 sm[];
    float2* bufA = sm;
    float2* bufB = sm + NFFT;
    float2* tw   = sm + 2 * NFFT;
    const int d0 = blockIdx.x * 2;

    for (int j = threadIdx.x; j < NFFT / 2; j += FFT_THREADS) {
        float sn, cs;
        sincosf((float)j * (-6.2831853071795864769f / (float)NFFT), &sn, &cs);
        tw[j] = make_float2(cs, sn);
        bufA[j] = make_float2(kk[(size_t)j * Dsz + d0], kk[(size_t)j * Dsz + d0 + 1]);
    }
    float2* Z = fft8192<true>(bufA, bufB, tw, false);
    float2* Ka = Kf + (size_t)d0 * 4097;
    float2* Kb = Ka + 4097;
    for (int k = threadIdx.x; k <= NFFT / 2; k += FFT_THREADS) {
        float2 z  = Z[k];
        float2 zc = Z[(NFFT - k) & (NFFT - 1)];
        Ka[k] = make_float2(0.5f * (z.x + zc.x), 0.5f * (z.y - zc.y));
        Kb[k] = make_float2(0.5f * (z.y + zc.y), 0.5f * (zc.x - z.x));
    }
}

__global__ __launch_bounds__(FFT_THREADS) void vfft_kernel(
    const float* __restrict__ vgT, const float* __restrict__ x0T,
    const float2* __restrict__ Kf, const float* __restrict__ fbias,
    float* __restrict__ yT)
{
    extern __shared__ float2 sm[];
    float2* bufA = sm;
    float2* bufB = sm + NFFT;
    float2* tw   = sm + 2 * NFFT;
    const int pair = blockIdx.x;
    const int b    = blockIdx.y;
    const int d0   = pair * 2;
    const float* v0 = vgT + ((size_t)(b * Dsz + d0)) * Lsz;
    const float* v1 = v0 + Lsz;

    for (int j = threadIdx.x; j < NFFT / 2; j += FFT_THREADS) {
        float sn, cs;
        sincosf((float)j * (-6.2831853071795864769f / (float)NFFT), &sn, &cs);
        tw[j] = make_float2(cs, sn);
        bufA[j] = make_float2(v0[j], v1[j]);
    }
    float2* Z = fft8192<true>(bufA, bufB, tw, false);   // == bufB
    float2* W = (Z == bufA) ? bufB : bufA;              // == bufA

    const float2* Ka = Kf + (size_t)d0 * 4097;
    const float2* Kb = Ka + 4097;
    for (int k = threadIdx.x; k <= NFFT / 2; k += FFT_THREADS) {
        float2 z  = Z[k];
        float2 zc = Z[(NFFT - k) & (NFFT - 1)];
        float2 Ak = make_float2(0.5f * (z.x + zc.x), 0.5f * (z.y - zc.y));
        float2 Bk = make_float2(0.5f * (z.y + zc.y), 0.5f * (zc.x - z.x));
        float2 Ya = cmulf(Ak, Ka[k]);
        float2 Yb = cmulf(Bk, Kb[k]);
        W[k] = make_float2(Ya.x - Yb.y, Ya.y + Yb.x);
        if (k != 0 && k != NFFT / 2)
            W[NFFT - k] = make_float2(Ya.x + Yb.y, Yb.x - Ya.y);
    }
    float2* res = fft8192<false>(W, Z, tw, true);       // unnormalized inverse

    const float invN = 1.0f / (float)NFFT;
    const float fb0 = fbias[d0], fb1 = fbias[d0 + 1];
    const float* x0a = x0T + ((size_t)(b * Dsz + d0)) * Lsz;
    const float* x0b = x0a + Lsz;
    float* ya = yT + ((size_t)(b * Dsz + d0)) * Lsz;
    float* yb = ya + Lsz;
    for (int t = threadIdx.x; t < Lsz; t += FFT_THREADS) {
        float2 w = res[t];
        ya[t] = (w.x * invN + fb0) * x0a[t];
        yb[t] = (w.y * invN + fb1) * x0b[t];
    }
}

// ---------------------------------------------------------------------------
// Launch
// ---------------------------------------------------------------------------
extern "C" void kernel_launch(void* const* d_in, const int* in_sizes, int n_in,
                              void* d_out, int out_size)
{
    const float* x       = (const float*)d_in[0];
    const float* W_in    = (const float*)d_in[1];
    const float* b_in    = (const float*)d_in[2];
    const float* short_w = (const float*)d_in[3];
    const float* short_b = (const float*)d_in[4];
    const float* W1      = (const float*)d_in[5];
    const float* b1      = (const float*)d_in[6];
    const float* f1      = (const float*)d_in[7];
    const float* W2      = (const float*)d_in[8];
    const float* b2      = (const float*)d_in[9];
    const float* f2      = (const float*)d_in[10];
    const float* W3      = (const float*)d_in[11];
    const float* b3      = (const float*)d_in[12];
    const float* fbias   = (const float*)d_in[13];
    const float* W_out   = (const float*)d_in[14];
    const float* b_out   = (const float*)d_in[15];
    float* out = (float*)d_out;

    float *p_x0, *p_vg, *p_kk, *p_y;
    float2* p_Kf;
    __half *p_u, *p_A1, *p_Bt1, *p_A2, *p_Bt2;
    cudaGetSymbolAddress((void**)&p_u,   g_u);
    cudaGetSymbolAddress((void**)&p_x0,  g_x0T);
    cudaGetSymbolAddress((void**)&p_vg,  g_vgT);
    cudaGetSymbolAddress((void**)&p_kk,  g_kk);
    cudaGetSymbolAddress((void**)&p_Kf,  g_Kf);
    cudaGetSymbolAddress((void**)&p_y,   g_yT);
    cudaGetSymbolAddress((void**)&p_A1,  g_A1);
    cudaGetSymbolAddress((void**)&p_Bt1, g_Bt1);
    cudaGetSymbolAddress((void**)&p_A2,  g_A2);
    cudaGetSymbolAddress((void**)&p_Bt2, g_Bt2);

    cudaFuncSetAttribute(kfft_kernel, cudaFuncAttributeMaxDynamicSharedMemorySize,
                         FFT_SMEM_BYTES);
    cudaFuncSetAttribute(vfft_kernel, cudaFuncAttributeMaxDynamicSharedMemorySize,
                         FFT_SMEM_BYTES);
    cudaFuncSetAttribute(gemm_f16_kernel<__half>,
                         cudaFuncAttributeMaxDynamicSharedMemorySize, GM_SMEM);
    cudaFuncSetAttribute(gemm_f16_kernel<float>,
                         cudaFuncAttributeMaxDynamicSharedMemorySize, GM_SMEM);

    // 1) operand conversion for GEMM1
    convert_a_kernel<<<(size_t)Msz * Dsz / 256, 256>>>(x, p_A1);
    convert_b_kernel<<<dim3(WIDTH / 32, Dsz / 32), 1024>>>(W_in, p_Bt1, WIDTH);

    // 2) u = x @ W_in + b_in  (fp16x2 mma.sync, fp16 output)
    gemm_f16_kernel<__half><<<dim3(WIDTH / 128, Msz / 128), 256, GM_SMEM>>>(
        p_A1, p_Bt1, b_in, p_u, Msz, WIDTH);

    // 3) short conv + gate -> x0T, vgT (transposed B,D,L)
    shortconv_kernel<<<dim3(Lsz / 64, Dsz / 32, Bsz), 256>>>(
        p_u, short_w, short_b, p_x0, p_vg);

    // 4) implicit filter (flipped + decayed)
    filter_kernel<<<Lsz, 256>>>(W1, b1, f1, W2, b2, f2, W3, b3, p_kk);

    // 5) filter spectra
    kfft_kernel<<<Dsz / 2, FFT_THREADS, FFT_SMEM_BYTES>>>(p_kk, p_Kf);

    // 6) FFT conv + bias + x0 gate
    vfft_kernel<<<dim3(Dsz / 2, Bsz), FFT_THREADS, FFT_SMEM_BYTES>>>(
        p_vg, p_x0, p_Kf, fbias, p_y);

    // 7) operand conversion for GEMM2
    convert_b_kernel<<<dim3(Dsz / 32, Dsz / 32), 1024>>>(W_out, p_Bt2, Dsz);
    convert_y_kernel<<<dim3(Lsz / 32, Dsz / 32, Bsz), 1024>>>(p_y, p_A2);

    // 8) out = y @ W_out + b_out  (fp16x2 mma.sync, fp32 output)
    gemm_f16_kernel<float><<<dim3(Dsz / 128, Msz / 128), 256, GM_SMEM>>>(
        p_A2, p_Bt2, b_out, out, Msz, Dsz);
}

// round 13
// speedup vs baseline: 1.0906x; 1.0556x over previous
#include <cuda_runtime.h>
#include <cuda_fp16.h>
#include <math.h>
#include <stddef.h>
#include <stdint.h>

// ---------------------------------------------------------------------------
// Problem constants
// ---------------------------------------------------------------------------
#define Bsz   4
#define Lsz   4096
#define Dsz   1024
#define WIDTH 3072
#define Msz   (Bsz * Lsz)      // 16384
#define NFFT  8192
#define FFT_THREADS 1024
#define FFT_SMEM_BYTES ((2 * NFFT + NFFT / 2) * (int)sizeof(float2))  // 163840

#define KAUG  2048             // 2 * 1024 augmented-K for fp16x2 GEMM (A side)
#define KB    1024             // B stores hi segment only

// ---------------------------------------------------------------------------
// Helpers (baseline PTX only: sm_80-compatible — harness targets compute_100)
// ---------------------------------------------------------------------------
__device__ __forceinline__ uint32_t smem_u32(const void* p) {
    uint32_t a;
    asm("{ .reg .u64 t; cvta.to.shared.u64 t, %1; cvt.u32.u64 %0, t; }"
        : "=r"(a) : "l"(p));
    return a;
}

__device__ __forceinline__ void cpa16(uint32_t s, const void* g) {
    asm volatile("cp.async.cg.shared.global [%0], [%1], 16;" :: "r"(s), "l"(g));
}

__device__ __forceinline__ void ldsm4(uint32_t* r, uint32_t a) {
    asm volatile("ldmatrix.sync.aligned.m8n8.x4.shared.b16 {%0,%1,%2,%3}, [%4];"
        : "=r"(r[0]), "=r"(r[1]), "=r"(r[2]), "=r"(r[3]) : "r"(a));
}

__device__ __forceinline__ void mma_f16(float* c, const uint32_t* a, const uint32_t* b) {
    asm volatile(
        "mma.sync.aligned.m16n8k16.row.col.f32.f16.f16.f32 "
        "{%0,%1,%2,%3}, {%4,%5,%6,%7}, {%8,%9}, {%0,%1,%2,%3};"
        : "+f"(c[0]), "+f"(c[1]), "+f"(c[2]), "+f"(c[3])
        : "r"(a[0]), "r"(a[1]), "r"(a[2]), "r"(a[3]), "r"(b[0]), "r"(b[1]));
}

// ---------------------------------------------------------------------------
// Scratch (static device globals; no allocation allowed)
// ---------------------------------------------------------------------------
__device__ __half g_u  [(size_t)Msz * WIDTH];       // (B*L, 3D) fp16 intermediate
__device__ float  g_x0T[(size_t)Bsz * Dsz * Lsz];   // (B, D, L)
__device__ float  g_vgT[(size_t)Bsz * Dsz * Lsz];   // (B, D, L)
__device__ float  g_kk [(size_t)Lsz * Dsz];         // flipped+decayed kernel
__device__ float2 g_Kf [(size_t)Dsz * 4097];        // per-channel spectrum
__device__ float  g_yT [(size_t)Bsz * Dsz * Lsz];   // (B, D, L)
__device__ __half g_A1 [(size_t)Msz * KAUG];        // [hi, lo] of x
__device__ __half g_Bt1[(size_t)WIDTH * KB];        // hi of W_in^T
__device__ __half g_A2 [(size_t)Msz * KAUG];        // [hi, lo] of y
__device__ __half g_Bt2[(size_t)Dsz * KB];          // hi of W_out^T

// ---------------------------------------------------------------------------
// fp16x2 mma.sync GEMM: C[M,N] = A'[M,2048] @ [Bhi,Bhi][N,2048]^T + bias
// BM=128, BN=128, BK=32, 256 thr, warp grid 2(m)x4(n), warp tile 64x32.
// 4-stage cp.async pipeline, XOR-swizzled smem, ldmatrix fragments.
// OutT = __half (intermediate u) or float (final out).
// ---------------------------------------------------------------------------
#define GS 4
#define STG 8192                       // bytes per operand stage (128 rows x 64B)
#define GM_SMEM (2 * GS * STG)         // 65536
#define NKI 64                         // 2048 / 32

template<typename OutT>
__global__ __launch_bounds__(256) void gemm_f16_kernel(
    const __half* __restrict__ A, const __half* __restrict__ Bw,
    const float* __restrict__ bias, OutT* __restrict__ C,
    const int M, const int N)
{
    extern __shared__ char gsm[];
    const uint32_t smA = smem_u32(gsm);
    const uint32_t smB = smA + GS * STG;

    const int tid = threadIdx.x;
    const int lid = tid & 31, wid = tid >> 5;
    const int wm = (wid & 1) * 64;      // warp m offset in tile
    const int wn = (wid >> 1) * 32;     // warp n offset in tile
    const int n0 = blockIdx.x * 128;
    const int m0 = blockIdx.y * 128;

    auto load_stage = [&](int buf, int k0) {
#pragma unroll
        for (int i = 0; i < 2; ++i) {
            int ch = tid + i * 256;               // 0..511
            int row = ch >> 2, c = ch & 3;
            uint32_t byte = (uint32_t)row * 64u + c * 16u;
            uint32_t sw = byte ^ ((row & 3) << 4);
            cpa16(smA + buf * STG + sw, A + (size_t)(m0 + row) * KAUG + k0 + c * 8);
        }
        const int kb = k0 & (KB - 1);
#pragma unroll
        for (int i = 0; i < 2; ++i) {
            int ch = tid + i * 256;
            int row = ch >> 2, c = ch & 3;
            uint32_t byte = (uint32_t)row * 64u + c * 16u;
            uint32_t sw = byte ^ ((row & 3) << 4);
            cpa16(smB + buf * STG + sw, Bw + (size_t)(n0 + row) * KB + kb + c * 8);
        }
        asm volatile("cp.async.commit_group;" ::: "memory");
    };

    float acc[4][4][4];
#pragma unroll
    for (int i = 0; i < 4; ++i)
#pragma unroll
        for (int j = 0; j < 4; ++j)
#pragma unroll
            for (int q = 0; q < 4; ++q) acc[i][j][q] = 0.f;

    for (int s = 0; s < GS - 1; ++s) load_stage(s, s * 32);

    for (int ks = 0; ks < NKI; ++ks) {
        if (ks + GS - 2 < NKI) asm volatile("cp.async.wait_group 2;" ::: "memory");
        else                   asm volatile("cp.async.wait_group 0;" ::: "memory");
        __syncthreads();
        const uint32_t sA = smA + (ks & (GS - 1)) * STG;
        const uint32_t sB = smB + (ks & (GS - 1)) * STG;
#pragma unroll
        for (int k2 = 0; k2 < 2; ++k2) {
            uint32_t af[4][4];
            uint32_t bfr[8];
#pragma unroll
            for (int tm = 0; tm < 4; ++tm) {
                int row = wm + tm * 16 + (lid & 15);
                uint32_t byte = (uint32_t)row * 64u + k2 * 32u + (lid >> 4) * 16u;
                ldsm4(af[tm], sA + (byte ^ ((row & 3) << 4)));
            }
#pragma unroll
            for (int tn2 = 0; tn2 < 2; ++tn2) {
                int row = wn + tn2 * 16 + ((lid >> 4) << 3) + (lid & 7);
                uint32_t byte = (uint32_t)row * 64u + k2 * 32u + ((lid >> 3) & 1) * 16u;
                ldsm4(&bfr[tn2 * 4], sB + (byte ^ ((row & 3) << 4)));
            }
#pragma unroll
            for (int tm = 0; tm < 4; ++tm)
#pragma unroll
                for (int tn = 0; tn < 4; ++tn)
                    mma_f16(acc[tm][tn], af[tm], &bfr[tn * 2]);
        }
        if (ks + GS - 1 < NKI) load_stage((ks + GS - 1) & (GS - 1), (ks + GS - 1) * 32);
    }

    // epilogue
#pragma unroll
    for (int tm = 0; tm < 4; ++tm) {
        int r0 = m0 + wm + tm * 16 + (lid >> 2);
#pragma unroll
        for (int tn = 0; tn < 4; ++tn) {
            int c = n0 + wn + tn * 8 + (lid & 3) * 2;
            float2 bv = *(const float2*)(bias + c);
            float v00 = acc[tm][tn][0] + bv.x, v01 = acc[tm][tn][1] + bv.y;
            float v10 = acc[tm][tn][2] + bv.x, v11 = acc[tm][tn][3] + bv.y;
            if (sizeof(OutT) == 2) {
                __half2* p0 = (__half2*)((__half*)C + (size_t)r0 * N + c);
                __half2* p1 = (__half2*)((__half*)C + (size_t)(r0 + 8) * N + c);
                *p0 = __floats2half2_rn(v00, v01);
                *p1 = __floats2half2_rn(v10, v11);
            } else {
                *(float2*)((float*)C + (size_t)r0 * N + c) = make_float2(v00, v01);
                *(float2*)((float*)C + (size_t)(r0 + 8) * N + c) = make_float2(v10, v11);
            }
        }
    }
}

// ---------------------------------------------------------------------------
// Conversion kernels: fp32 -> fp16 [hi, lo] (A side) / hi (B side)
// ---------------------------------------------------------------------------
__device__ __forceinline__ void split_f16(float x, __half& hi, __half& lo) {
    hi = __float2half_rn(x);
    lo = __float2half_rn(x - __half2float(hi));
}

// x (M x 1024 fp32 row-major) -> A' (M x 2048 fp16)
__global__ __launch_bounds__(256) void convert_a_kernel(
    const float* __restrict__ X, __half* __restrict__ Aout)
{
    const size_t idx = (size_t)blockIdx.x * 256 + threadIdx.x;
    const size_t m = idx >> 10;
    const int k = (int)(idx & 1023);
    float v = X[idx];
    __half hi, lo; split_f16(v, hi, lo);
    __half* row = Aout + m * KAUG;
    row[k] = hi; row[Dsz + k] = lo;
}

// W (1024 x N fp32) -> Bhi (N x 1024 fp16), transposed
__global__ __launch_bounds__(1024) void convert_b_kernel(
    const float* __restrict__ W, __half* __restrict__ Bout, const int N)
{
    __shared__ float sm[32][33];
    const int n0 = blockIdx.x * 32;
    const int k0 = blockIdx.y * 32;
    const int tx = threadIdx.x & 31, ty = threadIdx.x >> 5;
    sm[ty][tx] = W[(size_t)(k0 + ty) * N + n0 + tx];
    __syncthreads();
    const int n = n0 + ty, k = k0 + tx;
    Bout[(size_t)n * KB + k] = __float2half_rn(sm[tx][ty]);
}

// yT (B, D, L fp32) -> A' (M=B*L x 2048 fp16), transposed per batch
__global__ __launch_bounds__(1024) void convert_y_kernel(
    const float* __restrict__ yT, __half* __restrict__ Aout)
{
    __shared__ float sm[32][33];
    const int t0 = blockIdx.x * 32;
    const int d0 = blockIdx.y * 32;
    const int b  = blockIdx.z;
    const int tx = threadIdx.x & 31, ty = threadIdx.x >> 5;
    sm[ty][tx] = yT[((size_t)(b * Dsz + d0 + ty)) * Lsz + t0 + tx];
    __syncthreads();
    const int t = t0 + ty, d = d0 + tx;
    __half hi, lo; split_f16(sm[tx][ty], hi, lo);
    __half* row = Aout + ((size_t)(b * Lsz + t)) * KAUG;
    row[d] = hi; row[Dsz + d] = lo;
}

// ---------------------------------------------------------------------------
// Short depthwise conv (k=3, causal) + gate; writes transposed (B, D, L).
// (R9 mapping — measured fastest; input fp16, converted on smem fill.)
// ---------------------------------------------------------------------------
__global__ __launch_bounds__(256) void shortconv_kernel(
    const __half* __restrict__ u, const float* __restrict__ sw,
    const float* __restrict__ sb, float* __restrict__ x0T,
    float* __restrict__ vgT)
{
    __shared__ float s[3][66 * 33];
    const int t0 = blockIdx.x * 64;
    const int d0 = blockIdx.y * 32;
    const int b  = blockIdx.z;
    const int tid = threadIdx.x;

#pragma unroll 1
    for (int c = 0; c < 3; ++c) {
        const __half* up = u + (size_t)b * Lsz * WIDTH + c * Dsz + d0;
        for (int idx = tid; idx < 66 * 32; idx += 256) {
            int row = idx >> 5;
            int dc  = idx & 31;
            int t   = t0 - 2 + row;
            float v = (t >= 0) ? __half2float(up[(size_t)t * WIDTH + dc]) : 0.0f;
            s[c][row * 33 + dc] = v;
        }
    }
    __syncthreads();

    for (int idx = tid; idx < 64 * 32; idx += 256) {
        int dc = idx >> 6;
        int tt = idx & 63;
        int d  = d0 + dc;
        int t  = t0 + tt;
        const float* w0 = sw + (size_t)d * 3;
        const float* w1 = sw + (size_t)(Dsz + d) * 3;
        const float* w2 = sw + (size_t)(2 * Dsz + d) * 3;
        float c0 = s[0][tt * 33 + dc] * w0[0] + s[0][(tt + 1) * 33 + dc] * w0[1]
                 + s[0][(tt + 2) * 33 + dc] * w0[2] + sb[d];
        float c1 = s[1][tt * 33 + dc] * w1[0] + s[1][(tt + 1) * 33 + dc] * w1[1]
                 + s[1][(tt + 2) * 33 + dc] * w1[2] + sb[Dsz + d];
        float c2 = s[2][tt * 33 + dc] * w2[0] + s[2][(tt + 1) * 33 + dc] * w2[1]
                 + s[2][(tt + 2) * 33 + dc] * w2[2] + sb[2 * Dsz + d];
        size_t o = ((size_t)(b * Dsz + d)) * Lsz + t;
        x0T[o] = c0;
        vgT[o] = c2 * c1;
    }
}

// ---------------------------------------------------------------------------
// Filter MLP: one block per position i; writes flipped+decayed kernel
// ---------------------------------------------------------------------------
__global__ __launch_bounds__(256) void filter_kernel(
    const float* __restrict__ W1, const float* __restrict__ b1,
    const float* __restrict__ f1, const float* __restrict__ W2,
    const float* __restrict__ b2, const float* __restrict__ f2,
    const float* __restrict__ W3, const float* __restrict__ b3,
    float* __restrict__ kkout)
{
    __shared__ float h1[64], h2[64];
    const int i = blockIdx.x;
    const int tid = threadIdx.x;
    const float tn = (float)i * (1.0f / 4095.0f);
    const float phase = 1e-4f * (6.2831853071795864769f * (float)i / 4096.0f);

    if (tid < 64) {
        float sp, cp; sincosf(phase, &sp, &cp);
        float a = tn * W1[tid] + cp * W1[64 + tid] - sp * W1[128 + tid] + b1[tid];
        h1[tid] = sinf(a * f1[tid]);
    }
    __syncthreads();
    if (tid < 64) {
        float a = b2[tid];
#pragma unroll 8
        for (int c = 0; c < 64; ++c) a += h1[c] * W2[c * 64 + tid];
        h2[tid] = sinf(a * f2[tid]);
    }
    __syncthreads();

    const float dmax = -15.350567286626971f;  // log(0.01)/0.3
    const float dmin = -3.0701134573253943f;  // log(0.01)/1.5
    const int row = Lsz - 1 - i;
    for (int d = tid; d < Dsz; d += 256) {
        float a = b3[d];
#pragma unroll 8
        for (int c = 0; c < 64; ++c) a += h2[c] * W3[c * Dsz + d];
        float delta = fabsf(dmax + (dmin - dmax) * ((float)d * (1.0f / 1023.0f)));
        kkout[(size_t)row * Dsz + d] = a * expf(-tn * delta);
    }
}

// ---------------------------------------------------------------------------
// Stockham FFT, N=8192: 6 radix-4 passes + 1 trivial radix-2.
// PADDED=true: input upper half (indices 4096..8191) is implicitly zero and
// must NOT have been written; pass 0 then reads only the lower half.
// ---------------------------------------------------------------------------
template<bool PADDED>
__device__ __forceinline__ float2* fft8192(float2* buf0, float2* buf1,
                                           const float2* __restrict__ tw,
                                           bool inverse)
{
    float2* src = buf0;
    float2* dst = buf1;
#pragma unroll 1
    for (int p = 0; p < 6; ++p) {
        const int s = 1 << (2 * p);
        __syncthreads();
        if (PADDED && p == 0) {
            // B = D = 0: half the loads, q=0, m=i.
#pragma unroll
            for (int ii = 0; ii < NFFT / 4 / FFT_THREADS; ++ii) {
                const int i = threadIdx.x + ii * FFT_THREADS;
                float2 A = src[i];
                float2 C = src[i + 2048];
                float2 w1 = tw[i];
                float2 w2 = tw[2 * i];
                const float s1y = inverse ? -w1.y : w1.y;
                const float s2y = inverse ? -w2.y : w2.y;
                float2 jd = inverse ? make_float2(-C.y, C.x)
                                    : make_float2(C.y, -C.x);
                float2 t0 = make_float2(A.x + C.x, A.y + C.y);
                float2 t2 = make_float2(A.x - C.x, A.y - C.y);
                float2 t1 = make_float2(A.x + jd.x, A.y + jd.y);
                float2 t3 = make_float2(A.x - jd.x, A.y - jd.y);
                float2 o1 = make_float2(t1.x * w1.x - t1.y * s1y, t1.x * s1y + t1.y * w1.x);
                float2 o2 = make_float2(t2.x * w2.x - t2.y * s2y, t2.x * s2y + t2.y * w2.x);
                const float w3x = w1.x * w2.x - s1y * s2y;
                const float w3y = w1.x * s2y + s1y * w2.x;
                float2 o3 = make_float2(t3.x * w3x - t3.y * w3y, t3.x * w3y + t3.y * w3x);
                const int base = 4 * i;
                dst[base]     = t0;
                dst[base + 1] = o1;
                dst[base + 2] = o2;
                dst[base + 3] = o3;
            }
        } else {
#pragma unroll
            for (int ii = 0; ii < NFFT / 4 / FFT_THREADS; ++ii) {
                const int i = threadIdx.x + ii * FFT_THREADS;
                const int q = i & (s - 1);
                const int m = i - q;
                float2 A = src[i];
                float2 C = src[i + 2048];
                float2 B = src[i + 4096];
                float2 D = src[i + 6144];
                float2 w1 = tw[m];
                float2 w2 = tw[2 * m];
                const float s1y = inverse ? -w1.y : w1.y;
                const float s2y = inverse ? -w2.y : w2.y;
                float2 sAB = make_float2(A.x + B.x, A.y + B.y);
                float2 dAB = make_float2(A.x - B.x, A.y - B.y);
                float2 sCD = make_float2(C.x + D.x, C.y + D.y);
                float2 dCD = make_float2(C.x - D.x, C.y - D.y);
                float2 jd = inverse ? make_float2(-dCD.y, dCD.x)
                                    : make_float2(dCD.y, -dCD.x);
                float2 t0 = make_float2(sAB.x + sCD.x, sAB.y + sCD.y);
                float2 t2 = make_float2(sAB.x - sCD.x, sAB.y - sCD.y);
                float2 t1 = make_float2(dAB.x + jd.x, dAB.y + jd.y);
                float2 t3 = make_float2(dAB.x - jd.x, dAB.y - jd.y);
                float2 o1 = make_float2(t1.x * w1.x - t1.y * s1y, t1.x * s1y + t1.y * w1.x);
                float2 o2 = make_float2(t2.x * w2.x - t2.y * s2y, t2.x * s2y + t2.y * w2.x);
                const float w3x = w1.x * w2.x - s1y * s2y;
                const float w3y = w1.x * s2y + s1y * w2.x;
                float2 o3 = make_float2(t3.x * w3x - t3.y * w3y, t3.x * w3y + t3.y * w3x);
                const int base = 4 * m + q;
                dst[base]         = t0;
                dst[base + s]     = o1;
                dst[base + 2 * s] = o2;
                dst[base + 3 * s] = o3;
            }
        }
        float2* tmp = src; src = dst; dst = tmp;
    }
    // final radix-2 stage (s=4096): twiddle index is 0 -> w = 1
    __syncthreads();
#pragma unroll
    for (int ii = 0; ii < NFFT / 2 / FFT_THREADS; ++ii) {
        const int t = threadIdx.x + ii * FFT_THREADS;
        float2 a = src[t];
        float2 b = src[t + 4096];
        dst[t]        = make_float2(a.x + b.x, a.y + b.y);
        dst[t + 4096] = make_float2(a.x - b.x, a.y - b.y);
    }
    __syncthreads();
    return dst;
}

__device__ __forceinline__ float2 cmulf(float2 a, float2 b) {
    return make_float2(a.x * b.x - a.y * b.y, a.x * b.y + a.y * b.x);
}

__global__ __launch_bounds__(FFT_THREADS) void kfft_kernel(
    const float* __restrict__ kk, float2* __restrict__ Kf)
{
    extern __shared__ float2 sm[];
    float2* bufA = sm;
    float2* bufB = sm + NFFT;
    float2* tw   = sm + 2 * NFFT;
    const int d0 = blockIdx.x * 2;

    for (int j = threadIdx.x; j < NFFT / 2; j += FFT_THREADS) {
        float sn, cs;
        sincosf((float)j * (-6.2831853071795864769f / (float)NFFT), &sn, &cs);
        tw[j] = make_float2(cs, sn);
        bufA[j] = make_float2(kk[(size_t)j * Dsz + d0], kk[(size_t)j * Dsz + d0 + 1]);
    }
    float2* Z = fft8192<true>(bufA, bufB, tw, false);
    float2* Ka = Kf + (size_t)d0 * 4097;
    float2* Kb = Ka + 4097;
    for (int k = threadIdx.x; k <= NFFT / 2; k += FFT_THREADS) {
        float2 z  = Z[k];
        float2 zc = Z[(NFFT - k) & (NFFT - 1)];
        Ka[k] = make_float2(0.5f * (z.x + zc.x), 0.5f * (z.y - zc.y));
        Kb[k] = make_float2(0.5f * (z.y + zc.y), 0.5f * (zc.x - z.x));
    }
}

__global__ __launch_bounds__(FFT_THREADS) void vfft_kernel(
    const float* __restrict__ vgT, const float* __restrict__ x0T,
    const float2* __restrict__ Kf, const float* __restrict__ fbias,
    float* __restrict__ yT)
{
    extern __shared__ float2 sm[];
    float2* bufA = sm;
    float2* bufB = sm + NFFT;
    float2* tw   = sm + 2 * NFFT;
    const int pair = blockIdx.x;
    const int b    = blockIdx.y;
    const int d0   = pair * 2;
    const float* v0 = vgT + ((size_t)(b * Dsz + d0)) * Lsz;
    const float* v1 = v0 + Lsz;

    for (int j = threadIdx.x; j < NFFT / 2; j += FFT_THREADS) {
        float sn, cs;
        sincosf((float)j * (-6.2831853071795864769f / (float)NFFT), &sn, &cs);
        tw[j] = make_float2(cs, sn);
        bufA[j] = make_float2(v0[j], v1[j]);
    }
    float2* Z = fft8192<true>(bufA, bufB, tw, false);   // == bufB
    float2* W = (Z == bufA) ? bufB : bufA;              // == bufA

    const float2* Ka = Kf + (size_t)d0 * 4097;
    const float2* Kb = Ka + 4097;
    for (int k = threadIdx.x; k <= NFFT / 2; k += FFT_THREADS) {
        float2 z  = Z[k];
        float2 zc = Z[(NFFT - k) & (NFFT - 1)];
        float2 Ak = make_float2(0.5f * (z.x + zc.x), 0.5f * (z.y - zc.y));
        float2 Bk = make_float2(0.5f * (z.y + zc.y), 0.5f * (zc.x - z.x));
        float2 Ya = cmulf(Ak, Ka[k]);
        float2 Yb = cmulf(Bk, Kb[k]);
        W[k] = make_float2(Ya.x - Yb.y, Ya.y + Yb.x);
        if (k != 0 && k != NFFT / 2)
            W[NFFT - k] = make_float2(Ya.x + Yb.y, Yb.x - Ya.y);
    }
    float2* res = fft8192<false>(W, Z, tw, true);       // unnormalized inverse

    const float invN = 1.0f / (float)NFFT;
    const float fb0 = fbias[d0], fb1 = fbias[d0 + 1];
    const float* x0a = x0T + ((size_t)(b * Dsz + d0)) * Lsz;
    const float* x0b = x0a + Lsz;
    float* ya = yT + ((size_t)(b * Dsz + d0)) * Lsz;
    float* yb = ya + Lsz;
    for (int t = threadIdx.x; t < Lsz; t += FFT_THREADS) {
        float2 w = res[t];
        ya[t] = (w.x * invN + fb0) * x0a[t];
        yb[t] = (w.y * invN + fb1) * x0b[t];
    }
}

// ---------------------------------------------------------------------------
// Launch
// ---------------------------------------------------------------------------
extern "C" void kernel_launch(void* const* d_in, const int* in_sizes, int n_in,
                              void* d_out, int out_size)
{
    const float* x       = (const float*)d_in[0];
    const float* W_in    = (const float*)d_in[1];
    const float* b_in    = (const float*)d_in[2];
    const float* short_w = (const float*)d_in[3];
    const float* short_b = (const float*)d_in[4];
    const float* W1      = (const float*)d_in[5];
    const float* b1      = (const float*)d_in[6];
    const float* f1      = (const float*)d_in[7];
    const float* W2      = (const float*)d_in[8];
    const float* b2      = (const float*)d_in[9];
    const float* f2      = (const float*)d_in[10];
    const float* W3      = (const float*)d_in[11];
    const float* b3      = (const float*)d_in[12];
    const float* fbias   = (const float*)d_in[13];
    const float* W_out   = (const float*)d_in[14];
    const float* b_out   = (const float*)d_in[15];
    float* out = (float*)d_out;

    float *p_x0, *p_vg, *p_kk, *p_y;
    float2* p_Kf;
    __half *p_u, *p_A1, *p_Bt1, *p_A2, *p_Bt2;
    cudaGetSymbolAddress((void**)&p_u,   g_u);
    cudaGetSymbolAddress((void**)&p_x0,  g_x0T);
    cudaGetSymbolAddress((void**)&p_vg,  g_vgT);
    cudaGetSymbolAddress((void**)&p_kk,  g_kk);
    cudaGetSymbolAddress((void**)&p_Kf,  g_Kf);
    cudaGetSymbolAddress((void**)&p_y,   g_yT);
    cudaGetSymbolAddress((void**)&p_A1,  g_A1);
    cudaGetSymbolAddress((void**)&p_Bt1, g_Bt1);
    cudaGetSymbolAddress((void**)&p_A2,  g_A2);
    cudaGetSymbolAddress((void**)&p_Bt2, g_Bt2);

    cudaFuncSetAttribute(kfft_kernel, cudaFuncAttributeMaxDynamicSharedMemorySize,
                         FFT_SMEM_BYTES);
    cudaFuncSetAttribute(vfft_kernel, cudaFuncAttributeMaxDynamicSharedMemorySize,
                         FFT_SMEM_BYTES);
    cudaFuncSetAttribute(gemm_f16_kernel<__half>,
                         cudaFuncAttributeMaxDynamicSharedMemorySize, GM_SMEM);
    cudaFuncSetAttribute(gemm_f16_kernel<float>,
                         cudaFuncAttributeMaxDynamicSharedMemorySize, GM_SMEM);

    // 1) operand conversion for GEMM1
    convert_a_kernel<<<(size_t)Msz * Dsz / 256, 256>>>(x, p_A1);
    convert_b_kernel<<<dim3(WIDTH / 32, Dsz / 32), 1024>>>(W_in, p_Bt1, WIDTH);

    // 2) u = x @ W_in + b_in  (fp16x2 mma.sync, fp16 output)
    gemm_f16_kernel<__half><<<dim3(WIDTH / 128, Msz / 128), 256, GM_SMEM>>>(
        p_A1, p_Bt1, b_in, p_u, Msz, WIDTH);

    // 3) short conv + gate -> x0T, vgT (transposed B,D,L)
    shortconv_kernel<<<dim3(Lsz / 64, Dsz / 32, Bsz), 256>>>(
        p_u, short_w, short_b, p_x0, p_vg);

    // 4) implicit filter (flipped + decayed)
    filter_kernel<<<Lsz, 256>>>(W1, b1, f1, W2, b2, f2, W3, b3, p_kk);

    // 5) filter spectra
    kfft_kernel<<<Dsz / 2, FFT_THREADS, FFT_SMEM_BYTES>>>(p_kk, p_Kf);

    // 6) FFT conv + bias + x0 gate
    vfft_kernel<<<dim3(Dsz / 2, Bsz), FFT_THREADS, FFT_SMEM_BYTES>>>(
        p_vg, p_x0, p_Kf, fbias, p_y);

    // 7) operand conversion for GEMM2
    convert_b_kernel<<<dim3(Dsz / 32, Dsz / 32), 1024>>>(W_out, p_Bt2, Dsz);
    convert_y_kernel<<<dim3(Lsz / 32, Dsz / 32, Bsz), 1024>>>(p_y, p_A2);

    // 8) out = y @ W_out + b_out  (fp16x2 mma.sync, fp32 output)
    gemm_f16_kernel<float><<<dim3(Dsz / 128, Msz / 128), 256, GM_SMEM>>>(
        p_A2, p_Bt2, b_out, out, Msz, Dsz);
}

// round 14
// speedup vs baseline: 1.1843x; 1.0859x over previous
#include <cuda_runtime.h>
#include <cuda_fp16.h>
#include <math.h>
#include <stddef.h>
#include <stdint.h>

// ---------------------------------------------------------------------------
// Problem constants
// ---------------------------------------------------------------------------
#define Bsz   4
#define Lsz   4096
#define Dsz   1024
#define WIDTH 3072
#define Msz   (Bsz * Lsz)      // 16384
#define NFFT  8192
#define FFT_THREADS 1024
#define FFT_SMEM_BYTES ((2 * NFFT + NFFT / 2) * (int)sizeof(float2))  // 163840

#define KAUG  2048             // 2 * 1024 augmented-K for fp16x2 GEMM1 (A side)
#define KB    1024             // B stores hi segment only

// ---------------------------------------------------------------------------
// Helpers (baseline PTX only: sm_80-compatible — harness targets compute_100)
// ---------------------------------------------------------------------------
__device__ __forceinline__ uint32_t smem_u32(const void* p) {
    uint32_t a;
    asm("{ .reg .u64 t; cvta.to.shared.u64 t, %1; cvt.u32.u64 %0, t; }"
        : "=r"(a) : "l"(p));
    return a;
}

__device__ __forceinline__ void cpa16(uint32_t s, const void* g) {
    asm volatile("cp.async.cg.shared.global [%0], [%1], 16;" :: "r"(s), "l"(g));
}

__device__ __forceinline__ void ldsm4(uint32_t* r, uint32_t a) {
    asm volatile("ldmatrix.sync.aligned.m8n8.x4.shared.b16 {%0,%1,%2,%3}, [%4];"
        : "=r"(r[0]), "=r"(r[1]), "=r"(r[2]), "=r"(r[3]) : "r"(a));
}

__device__ __forceinline__ void mma_f16(float* c, const uint32_t* a, const uint32_t* b) {
    asm volatile(
        "mma.sync.aligned.m16n8k16.row.col.f32.f16.f16.f32 "
        "{%0,%1,%2,%3}, {%4,%5,%6,%7}, {%8,%9}, {%0,%1,%2,%3};"
        : "+f"(c[0]), "+f"(c[1]), "+f"(c[2]), "+f"(c[3])
        : "r"(a[0]), "r"(a[1]), "r"(a[2]), "r"(a[3]), "r"(b[0]), "r"(b[1]));
}

// ---------------------------------------------------------------------------
// Scratch (static device globals; no allocation allowed)
// ---------------------------------------------------------------------------
__device__ __half g_u  [(size_t)Msz * WIDTH];       // (B*L, 3D) fp16
__device__ __half g_x0T[(size_t)Bsz * Dsz * Lsz];   // (B, D, L) fp16
__device__ __half g_vgT[(size_t)Bsz * Dsz * Lsz];   // (B, D, L) fp16
__device__ float  g_kk [(size_t)Lsz * Dsz];         // flipped+decayed kernel
__device__ float2 g_Kf [(size_t)Dsz * 4097];        // per-channel spectrum
__device__ __half g_yT [(size_t)Bsz * Dsz * Lsz];   // (B, D, L) fp16
__device__ float2 g_twg[NFFT / 2];                  // precomputed twiddles
__device__ __half g_A1 [(size_t)Msz * KAUG];        // [hi, lo] of x
__device__ __half g_Bt1[(size_t)WIDTH * KB];        // hi of W_in^T
__device__ __half g_A2 [(size_t)Msz * KB];          // y (fp16, no split needed)
__device__ __half g_Bt2[(size_t)Dsz * KB];          // hi of W_out^T

// ---------------------------------------------------------------------------
// fp16 mma.sync GEMM: C[M,N] = A[M,KA] @ Bwrap[N,KA]^T + bias
// BM=128, BN=128, BK=32, 256 thr, warp grid 2(m)x4(n), warp tile 64x32.
// 4-stage cp.async pipeline, XOR-swizzled smem, ldmatrix fragments.
// B is wrapped mod KB (hi-only storage). OutT = __half or float.
// ---------------------------------------------------------------------------
#define GS 4
#define STG 8192                       // bytes per operand stage (128 rows x 64B)
#define GM_SMEM (2 * GS * STG)         // 65536

template<typename OutT>
__global__ __launch_bounds__(256) void gemm_f16_kernel(
    const __half* __restrict__ A, const __half* __restrict__ Bw,
    const float* __restrict__ bias, OutT* __restrict__ C,
    const int M, const int N, const int KA, const int nki)
{
    extern __shared__ char gsm[];
    const uint32_t smA = smem_u32(gsm);
    const uint32_t smB = smA + GS * STG;

    const int tid = threadIdx.x;
    const int lid = tid & 31, wid = tid >> 5;
    const int wm = (wid & 1) * 64;      // warp m offset in tile
    const int wn = (wid >> 1) * 32;     // warp n offset in tile
    const int n0 = blockIdx.x * 128;
    const int m0 = blockIdx.y * 128;

    auto load_stage = [&](int buf, int k0) {
#pragma unroll
        for (int i = 0; i < 2; ++i) {
            int ch = tid + i * 256;               // 0..511
            int row = ch >> 2, c = ch & 3;
            uint32_t byte = (uint32_t)row * 64u + c * 16u;
            uint32_t sw = byte ^ ((row & 3) << 4);
            cpa16(smA + buf * STG + sw, A + (size_t)(m0 + row) * KA + k0 + c * 8);
        }
        const int kb = k0 & (KB - 1);
#pragma unroll
        for (int i = 0; i < 2; ++i) {
            int ch = tid + i * 256;
            int row = ch >> 2, c = ch & 3;
            uint32_t byte = (uint32_t)row * 64u + c * 16u;
            uint32_t sw = byte ^ ((row & 3) << 4);
            cpa16(smB + buf * STG + sw, Bw + (size_t)(n0 + row) * KB + kb + c * 8);
        }
        asm volatile("cp.async.commit_group;" ::: "memory");
    };

    float acc[4][4][4];
#pragma unroll
    for (int i = 0; i < 4; ++i)
#pragma unroll
        for (int j = 0; j < 4; ++j)
#pragma unroll
            for (int q = 0; q < 4; ++q) acc[i][j][q] = 0.f;

    for (int s = 0; s < GS - 1; ++s) load_stage(s, s * 32);

    for (int ks = 0; ks < nki; ++ks) {
        if (ks + GS - 2 < nki) asm volatile("cp.async.wait_group 2;" ::: "memory");
        else                   asm volatile("cp.async.wait_group 0;" ::: "memory");
        __syncthreads();
        const uint32_t sA = smA + (ks & (GS - 1)) * STG;
        const uint32_t sB = smB + (ks & (GS - 1)) * STG;
#pragma unroll
        for (int k2 = 0; k2 < 2; ++k2) {
            uint32_t af[4][4];
            uint32_t bfr[8];
#pragma unroll
            for (int tm = 0; tm < 4; ++tm) {
                int row = wm + tm * 16 + (lid & 15);
                uint32_t byte = (uint32_t)row * 64u + k2 * 32u + (lid >> 4) * 16u;
                ldsm4(af[tm], sA + (byte ^ ((row & 3) << 4)));
            }
#pragma unroll
            for (int tn2 = 0; tn2 < 2; ++tn2) {
                int row = wn + tn2 * 16 + ((lid >> 4) << 3) + (lid & 7);
                uint32_t byte = (uint32_t)row * 64u + k2 * 32u + ((lid >> 3) & 1) * 16u;
                ldsm4(&bfr[tn2 * 4], sB + (byte ^ ((row & 3) << 4)));
            }
#pragma unroll
            for (int tm = 0; tm < 4; ++tm)
#pragma unroll
                for (int tn = 0; tn < 4; ++tn)
                    mma_f16(acc[tm][tn], af[tm], &bfr[tn * 2]);
        }
        if (ks + GS - 1 < nki) load_stage((ks + GS - 1) & (GS - 1), (ks + GS - 1) * 32);
    }

    // epilogue
#pragma unroll
    for (int tm = 0; tm < 4; ++tm) {
        int r0 = m0 + wm + tm * 16 + (lid >> 2);
#pragma unroll
        for (int tn = 0; tn < 4; ++tn) {
            int c = n0 + wn + tn * 8 + (lid & 3) * 2;
            float2 bv = *(const float2*)(bias + c);
            float v00 = acc[tm][tn][0] + bv.x, v01 = acc[tm][tn][1] + bv.y;
            float v10 = acc[tm][tn][2] + bv.x, v11 = acc[tm][tn][3] + bv.y;
            if (sizeof(OutT) == 2) {
                __half2* p0 = (__half2*)((__half*)C + (size_t)r0 * N + c);
                __half2* p1 = (__half2*)((__half*)C + (size_t)(r0 + 8) * N + c);
                *p0 = __floats2half2_rn(v00, v01);
                *p1 = __floats2half2_rn(v10, v11);
            } else {
                *(float2*)((float*)C + (size_t)r0 * N + c) = make_float2(v00, v01);
                *(float2*)((float*)C + (size_t)(r0 + 8) * N + c) = make_float2(v10, v11);
            }
        }
    }
}

// ---------------------------------------------------------------------------
// Twiddle precompute (once per launch; exact same sincosf values)
// ---------------------------------------------------------------------------
__global__ __launch_bounds__(1024) void twiddle_kernel(float2* __restrict__ tw)
{
    const int j = blockIdx.x * 1024 + threadIdx.x;
    float sn, cs;
    sincosf((float)j * (-6.2831853071795864769f / (float)NFFT), &sn, &cs);
    tw[j] = make_float2(cs, sn);
}

// ---------------------------------------------------------------------------
// Conversion kernels
// ---------------------------------------------------------------------------
__device__ __forceinline__ void split_f16(float x, __half& hi, __half& lo) {
    hi = __float2half_rn(x);
    lo = __float2half_rn(x - __half2float(hi));
}

// x (M x 1024 fp32 row-major) -> A' (M x 2048 fp16 [hi, lo])
__global__ __launch_bounds__(256) void convert_a_kernel(
    const float* __restrict__ X, __half* __restrict__ Aout)
{
    const size_t idx = (size_t)blockIdx.x * 256 + threadIdx.x;
    const size_t m = idx >> 10;
    const int k = (int)(idx & 1023);
    float v = X[idx];
    __half hi, lo; split_f16(v, hi, lo);
    __half* row = Aout + m * KAUG;
    row[k] = hi; row[Dsz + k] = lo;
}

// W (1024 x N fp32) -> Bhi (N x 1024 fp16), transposed
__global__ __launch_bounds__(1024) void convert_b_kernel(
    const float* __restrict__ W, __half* __restrict__ Bout, const int N)
{
    __shared__ float sm[32][33];
    const int n0 = blockIdx.x * 32;
    const int k0 = blockIdx.y * 32;
    const int tx = threadIdx.x & 31, ty = threadIdx.x >> 5;
    sm[ty][tx] = W[(size_t)(k0 + ty) * N + n0 + tx];
    __syncthreads();
    const int n = n0 + ty, k = k0 + tx;
    Bout[(size_t)n * KB + k] = __float2half_rn(sm[tx][ty]);
}

// yT (B, D, L fp16) -> A2 (M=B*L x 1024 fp16), pure transpose (exact)
__global__ __launch_bounds__(1024) void convert_y_kernel(
    const __half* __restrict__ yT, __half* __restrict__ Aout)
{
    __shared__ float sm[32][33];
    const int t0 = blockIdx.x * 32;
    const int d0 = blockIdx.y * 32;
    const int b  = blockIdx.z;
    const int tx = threadIdx.x & 31, ty = threadIdx.x >> 5;
    sm[ty][tx] = __half2float(yT[((size_t)(b * Dsz + d0 + ty)) * Lsz + t0 + tx]);
    __syncthreads();
    const int t = t0 + ty, d = d0 + tx;
    Aout[((size_t)(b * Lsz + t)) * KB + d] = __float2half_rn(sm[tx][ty]);
}

// ---------------------------------------------------------------------------
// Short depthwise conv (k=3, causal) + gate; writes fp16 transposed (B, D, L)
// ---------------------------------------------------------------------------
__global__ __launch_bounds__(256) void shortconv_kernel(
    const __half* __restrict__ u, const float* __restrict__ sw,
    const float* __restrict__ sb, __half* __restrict__ x0T,
    __half* __restrict__ vgT)
{
    __shared__ float s[3][66 * 33];
    const int t0 = blockIdx.x * 64;
    const int d0 = blockIdx.y * 32;
    const int b  = blockIdx.z;
    const int tid = threadIdx.x;

#pragma unroll 1
    for (int c = 0; c < 3; ++c) {
        const __half* up = u + (size_t)b * Lsz * WIDTH + c * Dsz + d0;
        for (int idx = tid; idx < 66 * 32; idx += 256) {
            int row = idx >> 5;
            int dc  = idx & 31;
            int t   = t0 - 2 + row;
            float v = (t >= 0) ? __half2float(up[(size_t)t * WIDTH + dc]) : 0.0f;
            s[c][row * 33 + dc] = v;
        }
    }
    __syncthreads();

    for (int idx = tid; idx < 64 * 32; idx += 256) {
        int dc = idx >> 6;
        int tt = idx & 63;
        int d  = d0 + dc;
        int t  = t0 + tt;
        const float* w0 = sw + (size_t)d * 3;
        const float* w1 = sw + (size_t)(Dsz + d) * 3;
        const float* w2 = sw + (size_t)(2 * Dsz + d) * 3;
        float c0 = s[0][tt * 33 + dc] * w0[0] + s[0][(tt + 1) * 33 + dc] * w0[1]
                 + s[0][(tt + 2) * 33 + dc] * w0[2] + sb[d];
        float c1 = s[1][tt * 33 + dc] * w1[0] + s[1][(tt + 1) * 33 + dc] * w1[1]
                 + s[1][(tt + 2) * 33 + dc] * w1[2] + sb[Dsz + d];
        float c2 = s[2][tt * 33 + dc] * w2[0] + s[2][(tt + 1) * 33 + dc] * w2[1]
                 + s[2][(tt + 2) * 33 + dc] * w2[2] + sb[2 * Dsz + d];
        size_t o = ((size_t)(b * Dsz + d)) * Lsz + t;
        x0T[o] = __float2half_rn(c0);
        vgT[o] = __float2half_rn(c2 * c1);
    }
}

// ---------------------------------------------------------------------------
// Filter MLP: one block per position i; writes flipped+decayed kernel
// ---------------------------------------------------------------------------
__global__ __launch_bounds__(256) void filter_kernel(
    const float* __restrict__ W1, const float* __restrict__ b1,
    const float* __restrict__ f1, const float* __restrict__ W2,
    const float* __restrict__ b2, const float* __restrict__ f2,
    const float* __restrict__ W3, const float* __restrict__ b3,
    float* __restrict__ kkout)
{
    __shared__ float h1[64], h2[64];
    const int i = blockIdx.x;
    const int tid = threadIdx.x;
    const float tn = (float)i * (1.0f / 4095.0f);
    const float phase = 1e-4f * (6.2831853071795864769f * (float)i / 4096.0f);

    if (tid < 64) {
        float sp, cp; sincosf(phase, &sp, &cp);
        float a = tn * W1[tid] + cp * W1[64 + tid] - sp * W1[128 + tid] + b1[tid];
        h1[tid] = sinf(a * f1[tid]);
    }
    __syncthreads();
    if (tid < 64) {
        float a = b2[tid];
#pragma unroll 8
        for (int c = 0; c < 64; ++c) a += h1[c] * W2[c * 64 + tid];
        h2[tid] = sinf(a * f2[tid]);
    }
    __syncthreads();

    const float dmax = -15.350567286626971f;  // log(0.01)/0.3
    const float dmin = -3.0701134573253943f;  // log(0.01)/1.5
    const int row = Lsz - 1 - i;
    for (int d = tid; d < Dsz; d += 256) {
        float a = b3[d];
#pragma unroll 8
        for (int c = 0; c < 64; ++c) a += h2[c] * W3[c * Dsz + d];
        float delta = fabsf(dmax + (dmin - dmax) * ((float)d * (1.0f / 1023.0f)));
        kkout[(size_t)row * Dsz + d] = a * expf(-tn * delta);
    }
}

// ---------------------------------------------------------------------------
// Stockham FFT, N=8192: 6 radix-4 passes + 1 trivial radix-2.
// PADDED=true: input upper half implicitly zero (not written).
// ---------------------------------------------------------------------------
template<bool PADDED>
__device__ __forceinline__ float2* fft8192(float2* buf0, float2* buf1,
                                           const float2* __restrict__ tw,
                                           bool inverse)
{
    float2* src = buf0;
    float2* dst = buf1;
#pragma unroll 1
    for (int p = 0; p < 6; ++p) {
        const int s = 1 << (2 * p);
        __syncthreads();
        if (PADDED && p == 0) {
#pragma unroll
            for (int ii = 0; ii < NFFT / 4 / FFT_THREADS; ++ii) {
                const int i = threadIdx.x + ii * FFT_THREADS;
                float2 A = src[i];
                float2 C = src[i + 2048];
                float2 w1 = tw[i];
                float2 w2 = tw[2 * i];
                const float s1y = inverse ? -w1.y : w1.y;
                const float s2y = inverse ? -w2.y : w2.y;
                float2 jd = inverse ? make_float2(-C.y, C.x)
                                    : make_float2(C.y, -C.x);
                float2 t0 = make_float2(A.x + C.x, A.y + C.y);
                float2 t2 = make_float2(A.x - C.x, A.y - C.y);
                float2 t1 = make_float2(A.x + jd.x, A.y + jd.y);
                float2 t3 = make_float2(A.x - jd.x, A.y - jd.y);
                float2 o1 = make_float2(t1.x * w1.x - t1.y * s1y, t1.x * s1y + t1.y * w1.x);
                float2 o2 = make_float2(t2.x * w2.x - t2.y * s2y, t2.x * s2y + t2.y * w2.x);
                const float w3x = w1.x * w2.x - s1y * s2y;
                const float w3y = w1.x * s2y + s1y * w2.x;
                float2 o3 = make_float2(t3.x * w3x - t3.y * w3y, t3.x * w3y + t3.y * w3x);
                const int base = 4 * i;
                dst[base]     = t0;
                dst[base + 1] = o1;
                dst[base + 2] = o2;
                dst[base + 3] = o3;
            }
        } else {
#pragma unroll
            for (int ii = 0; ii < NFFT / 4 / FFT_THREADS; ++ii) {
                const int i = threadIdx.x + ii * FFT_THREADS;
                const int q = i & (s - 1);
                const int m = i - q;
                float2 A = src[i];
                float2 C = src[i + 2048];
                float2 B = src[i + 4096];
                float2 D = src[i + 6144];
                float2 w1 = tw[m];
                float2 w2 = tw[2 * m];
                const float s1y = inverse ? -w1.y : w1.y;
                const float s2y = inverse ? -w2.y : w2.y;
                float2 sAB = make_float2(A.x + B.x, A.y + B.y);
                float2 dAB = make_float2(A.x - B.x, A.y - B.y);
                float2 sCD = make_float2(C.x + D.x, C.y + D.y);
                float2 dCD = make_float2(C.x - D.x, C.y - D.y);
                float2 jd = inverse ? make_float2(-dCD.y, dCD.x)
                                    : make_float2(dCD.y, -dCD.x);
                float2 t0 = make_float2(sAB.x + sCD.x, sAB.y + sCD.y);
                float2 t2 = make_float2(sAB.x - sCD.x, sAB.y - sCD.y);
                float2 t1 = make_float2(dAB.x + jd.x, dAB.y + jd.y);
                float2 t3 = make_float2(dAB.x - jd.x, dAB.y - jd.y);
                float2 o1 = make_float2(t1.x * w1.x - t1.y * s1y, t1.x * s1y + t1.y * w1.x);
                float2 o2 = make_float2(t2.x * w2.x - t2.y * s2y, t2.x * s2y + t2.y * w2.x);
                const float w3x = w1.x * w2.x - s1y * s2y;
                const float w3y = w1.x * s2y + s1y * w2.x;
                float2 o3 = make_float2(t3.x * w3x - t3.y * w3y, t3.x * w3y + t3.y * w3x);
                const int base = 4 * m + q;
                dst[base]         = t0;
                dst[base + s]     = o1;
                dst[base + 2 * s] = o2;
                dst[base + 3 * s] = o3;
            }
        }
        float2* tmp = src; src = dst; dst = tmp;
    }
    // final radix-2 stage (s=4096): w = 1
    __syncthreads();
#pragma unroll
    for (int ii = 0; ii < NFFT / 2 / FFT_THREADS; ++ii) {
        const int t = threadIdx.x + ii * FFT_THREADS;
        float2 a = src[t];
        float2 b = src[t + 4096];
        dst[t]        = make_float2(a.x + b.x, a.y + b.y);
        dst[t + 4096] = make_float2(a.x - b.x, a.y - b.y);
    }
    __syncthreads();
    return dst;
}

__device__ __forceinline__ float2 cmulf(float2 a, float2 b) {
    return make_float2(a.x * b.x - a.y * b.y, a.x * b.y + a.y * b.x);
}

__global__ __launch_bounds__(FFT_THREADS) void kfft_kernel(
    const float* __restrict__ kk, const float2* __restrict__ twg,
    float2* __restrict__ Kf)
{
    extern __shared__ float2 sm[];
    float2* bufA = sm;
    float2* bufB = sm + NFFT;
    float2* tw   = sm + 2 * NFFT;
    const int d0 = blockIdx.x * 2;

    for (int j = threadIdx.x; j < NFFT / 2; j += FFT_THREADS) {
        tw[j] = twg[j];
        bufA[j] = make_float2(kk[(size_t)j * Dsz + d0], kk[(size_t)j * Dsz + d0 + 1]);
    }
    float2* Z = fft8192<true>(bufA, bufB, tw, false);
    float2* Ka = Kf + (size_t)d0 * 4097;
    float2* Kb = Ka + 4097;
    for (int k = threadIdx.x; k <= NFFT / 2; k += FFT_THREADS) {
        float2 z  = Z[k];
        float2 zc = Z[(NFFT - k) & (NFFT - 1)];
        Ka[k] = make_float2(0.5f * (z.x + zc.x), 0.5f * (z.y - zc.y));
        Kb[k] = make_float2(0.5f * (z.y + zc.y), 0.5f * (zc.x - z.x));
    }
}

__global__ __launch_bounds__(FFT_THREADS) void vfft_kernel(
    const __half* __restrict__ vgT, const __half* __restrict__ x0T,
    const float2* __restrict__ twg,
    const float2* __restrict__ Kf, const float* __restrict__ fbias,
    __half* __restrict__ yT)
{
    extern __shared__ float2 sm[];
    float2* bufA = sm;
    float2* bufB = sm + NFFT;
    float2* tw   = sm + 2 * NFFT;
    const int pair = blockIdx.x;
    const int b    = blockIdx.y;
    const int d0   = pair * 2;
    const __half* v0 = vgT + ((size_t)(b * Dsz + d0)) * Lsz;
    const __half* v1 = v0 + Lsz;

    for (int j = threadIdx.x; j < NFFT / 2; j += FFT_THREADS) {
        tw[j] = twg[j];
        bufA[j] = make_float2(__half2float(v0[j]), __half2float(v1[j]));
    }
    float2* Z = fft8192<true>(bufA, bufB, tw, false);   // == bufB
    float2* W = (Z == bufA) ? bufB : bufA;              // == bufA

    const float2* Ka = Kf + (size_t)d0 * 4097;
    const float2* Kb = Ka + 4097;
    for (int k = threadIdx.x; k <= NFFT / 2; k += FFT_THREADS) {
        float2 z  = Z[k];
        float2 zc = Z[(NFFT - k) & (NFFT - 1)];
        float2 Ak = make_float2(0.5f * (z.x + zc.x), 0.5f * (z.y - zc.y));
        float2 Bk = make_float2(0.5f * (z.y + zc.y), 0.5f * (zc.x - z.x));
        float2 Ya = cmulf(Ak, Ka[k]);
        float2 Yb = cmulf(Bk, Kb[k]);
        W[k] = make_float2(Ya.x - Yb.y, Ya.y + Yb.x);
        if (k != 0 && k != NFFT / 2)
            W[NFFT - k] = make_float2(Ya.x + Yb.y, Yb.x - Ya.y);
    }
    float2* res = fft8192<false>(W, Z, tw, true);       // unnormalized inverse

    const float invN = 1.0f / (float)NFFT;
    const float fb0 = fbias[d0], fb1 = fbias[d0 + 1];
    const __half* x0a = x0T + ((size_t)(b * Dsz + d0)) * Lsz;
    const __half* x0b = x0a + Lsz;
    __half* ya = yT + ((size_t)(b * Dsz + d0)) * Lsz;
    __half* yb = ya + Lsz;
    for (int t = threadIdx.x; t < Lsz; t += FFT_THREADS) {
        float2 w = res[t];
        ya[t] = __float2half_rn((w.x * invN + fb0) * __half2float(x0a[t]));
        yb[t] = __float2half_rn((w.y * invN + fb1) * __half2float(x0b[t]));
    }
}

// ---------------------------------------------------------------------------
// Launch
// ---------------------------------------------------------------------------
extern "C" void kernel_launch(void* const* d_in, const int* in_sizes, int n_in,
                              void* d_out, int out_size)
{
    const float* x       = (const float*)d_in[0];
    const float* W_in    = (const float*)d_in[1];
    const float* b_in    = (const float*)d_in[2];
    const float* short_w = (const float*)d_in[3];
    const float* short_b = (const float*)d_in[4];
    const float* W1      = (const float*)d_in[5];
    const float* b1      = (const float*)d_in[6];
    const float* f1      = (const float*)d_in[7];
    const float* W2      = (const float*)d_in[8];
    const float* b2      = (const float*)d_in[9];
    const float* f2      = (const float*)d_in[10];
    const float* W3      = (const float*)d_in[11];
    const float* b3      = (const float*)d_in[12];
    const float* fbias   = (const float*)d_in[13];
    const float* W_out   = (const float*)d_in[14];
    const float* b_out   = (const float*)d_in[15];
    float* out = (float*)d_out;

    float *p_kk;
    float2 *p_Kf, *p_tw;
    __half *p_u, *p_x0, *p_vg, *p_y, *p_A1, *p_Bt1, *p_A2, *p_Bt2;
    cudaGetSymbolAddress((void**)&p_u,   g_u);
    cudaGetSymbolAddress((void**)&p_x0,  g_x0T);
    cudaGetSymbolAddress((void**)&p_vg,  g_vgT);
    cudaGetSymbolAddress((void**)&p_kk,  g_kk);
    cudaGetSymbolAddress((void**)&p_Kf,  g_Kf);
    cudaGetSymbolAddress((void**)&p_y,   g_yT);
    cudaGetSymbolAddress((void**)&p_tw,  g_twg);
    cudaGetSymbolAddress((void**)&p_A1,  g_A1);
    cudaGetSymbolAddress((void**)&p_Bt1, g_Bt1);
    cudaGetSymbolAddress((void**)&p_A2,  g_A2);
    cudaGetSymbolAddress((void**)&p_Bt2, g_Bt2);

    cudaFuncSetAttribute(kfft_kernel, cudaFuncAttributeMaxDynamicSharedMemorySize,
                         FFT_SMEM_BYTES);
    cudaFuncSetAttribute(vfft_kernel, cudaFuncAttributeMaxDynamicSharedMemorySize,
                         FFT_SMEM_BYTES);
    cudaFuncSetAttribute(gemm_f16_kernel<__half>,
                         cudaFuncAttributeMaxDynamicSharedMemorySize, GM_SMEM);
    cudaFuncSetAttribute(gemm_f16_kernel<float>,
                         cudaFuncAttributeMaxDynamicSharedMemorySize, GM_SMEM);

    // 0) twiddle table
    twiddle_kernel<<<NFFT / 2 / 1024, 1024>>>(p_tw);

    // 1) operand conversion for GEMM1
    convert_a_kernel<<<(size_t)Msz * Dsz / 256, 256>>>(x, p_A1);
    convert_b_kernel<<<dim3(WIDTH / 32, Dsz / 32), 1024>>>(W_in, p_Bt1, WIDTH);

    // 2) u = x @ W_in + b_in  (fp16x2, K'=2048, fp16 output)
    gemm_f16_kernel<__half><<<dim3(WIDTH / 128, Msz / 128), 256, GM_SMEM>>>(
        p_A1, p_Bt1, b_in, p_u, Msz, WIDTH, KAUG, 64);

    // 3) short conv + gate -> x0T, vgT (fp16, transposed B,D,L)
    shortconv_kernel<<<dim3(Lsz / 64, Dsz / 32, Bsz), 256>>>(
        p_u, short_w, short_b, p_x0, p_vg);

    // 4) implicit filter (flipped + decayed)
    filter_kernel<<<Lsz, 256>>>(W1, b1, f1, W2, b2, f2, W3, b3, p_kk);

    // 5) filter spectra
    kfft_kernel<<<Dsz / 2, FFT_THREADS, FFT_SMEM_BYTES>>>(p_kk, p_tw, p_Kf);

    // 6) FFT conv + bias + x0 gate -> yT fp16
    vfft_kernel<<<dim3(Dsz / 2, Bsz), FFT_THREADS, FFT_SMEM_BYTES>>>(
        p_vg, p_x0, p_tw, p_Kf, fbias, p_y);

    // 7) operand conversion for GEMM2 (y transpose is exact fp16 copy)
    convert_b_kernel<<<dim3(Dsz / 32, Dsz / 32), 1024>>>(W_out, p_Bt2, Dsz);
    convert_y_kernel<<<dim3(Lsz / 32, Dsz / 32, Bsz), 1024>>>(p_y, p_A2);

    // 8) out = y @ W_out + b_out  (fp16, K=1024 — y already fp16, no split)
    gemm_f16_kernel<float><<<dim3(Dsz / 128, Msz / 128), 256, GM_SMEM>>>(
        p_A2, p_Bt2, b_out, out, Msz, Dsz, KB, 32);
}

// round 17
// speedup vs baseline: 1.4015x; 1.1835x over previous
#include <cuda_runtime.h>
#include <cuda_fp16.h>
#include <math.h>
#include <stddef.h>
#include <stdint.h>

// ---------------------------------------------------------------------------
// Problem constants
// ---------------------------------------------------------------------------
#define Bsz   4
#define Lsz   4096
#define Dsz   1024
#define WIDTH 3072
#define Msz   (Bsz * Lsz)      // 16384
#define NFFT  8192
#define FFT_THREADS 1024
#define FFT_SMEM_BYTES ((2 * NFFT + NFFT / 2) * (int)sizeof(float2))  // 163840

#define KAUG  2048             // 2 * 1024 augmented-K for fp16x2 GEMM1 (A side)
#define KB    1024             // B stores hi segment only

// ---------------------------------------------------------------------------
// Helpers (baseline PTX only: sm_80-compatible — harness targets compute_100)
// ---------------------------------------------------------------------------
__device__ __forceinline__ uint32_t smem_u32(const void* p) {
    uint32_t a;
    asm("{ .reg .u64 t; cvta.to.shared.u64 t, %1; cvt.u32.u64 %0, t; }"
        : "=r"(a) : "l"(p));
    return a;
}

__device__ __forceinline__ void cpa16(uint32_t s, const void* g) {
    asm volatile("cp.async.cg.shared.global [%0], [%1], 16;" :: "r"(s), "l"(g));
}

__device__ __forceinline__ void ldsm4(uint32_t* r, uint32_t a) {
    asm volatile("ldmatrix.sync.aligned.m8n8.x4.shared.b16 {%0,%1,%2,%3}, [%4];"
        : "=r"(r[0]), "=r"(r[1]), "=r"(r[2]), "=r"(r[3]) : "r"(a));
}

__device__ __forceinline__ void mma_f16(float* c, const uint32_t* a, const uint32_t* b) {
    asm volatile(
        "mma.sync.aligned.m16n8k16.row.col.f32.f16.f16.f32 "
        "{%0,%1,%2,%3}, {%4,%5,%6,%7}, {%8,%9}, {%0,%1,%2,%3};"
        : "+f"(c[0]), "+f"(c[1]), "+f"(c[2]), "+f"(c[3])
        : "r"(a[0]), "r"(a[1]), "r"(a[2]), "r"(a[3]), "r"(b[0]), "r"(b[1]));
}

// Swizzle<2,3,3> for 64-byte rows: XOR 16B-slot with (row>>1)&3.
// Conflict-free ldmatrix: even rows and odd rows each hit 4 distinct slots.
__device__ __forceinline__ uint32_t swz64(uint32_t byte) {
    return byte ^ ((byte >> 3) & 0x30u);
}

// ---------------------------------------------------------------------------
// Scratch (static device globals; no allocation allowed)
// ---------------------------------------------------------------------------
__device__ __half g_u  [(size_t)Msz * WIDTH];       // (B*L, 3D) fp16
__device__ __half g_x0T[(size_t)Bsz * Dsz * Lsz];   // (B, D, L) fp16
__device__ __half g_vgT[(size_t)Bsz * Dsz * Lsz];   // (B, D, L) fp16
__device__ float  g_kk [(size_t)Lsz * Dsz];         // flipped+decayed kernel
__device__ float2 g_Kf [(size_t)Dsz * 4097];        // per-channel spectrum
__device__ __half g_yT [(size_t)Bsz * Dsz * Lsz];   // (B, D, L) fp16
__device__ float2 g_twg[NFFT / 2];                  // precomputed twiddles
__device__ __half g_A1 [(size_t)Msz * KAUG];        // [hi, lo] of x
__device__ __half g_Bt1[(size_t)WIDTH * KB];        // hi of W_in^T
__device__ __half g_A2 [(size_t)Msz * KB];          // y (fp16, no split needed)
__device__ __half g_Bt2[(size_t)Dsz * KB];          // hi of W_out^T

// ---------------------------------------------------------------------------
// fp16 mma.sync GEMM: C[M,N] = A[M,KA] @ Bwrap[N,KA]^T + bias
// BM=128, BN=128, BK=32, 256 thr, warp grid 2(m)x4(n), warp tile 64x32.
// 4-stage cp.async pipeline, Swizzle<2,3,3> smem, ldmatrix fragments.
// B is wrapped mod KB (hi-only storage). OutT = __half or float.
// ---------------------------------------------------------------------------
#define GS 4
#define STG 8192                       // bytes per operand stage (128 rows x 64B)
#define GM_SMEM (2 * GS * STG)         // 65536

template<typename OutT>
__global__ __launch_bounds__(256) void gemm_f16_kernel(
    const __half* __restrict__ A, const __half* __restrict__ Bw,
    const float* __restrict__ bias, OutT* __restrict__ C,
    const int M, const int N, const int KA, const int nki)
{
    extern __shared__ char gsm[];
    const uint32_t smA = smem_u32(gsm);
    const uint32_t smB = smA + GS * STG;

    const int tid = threadIdx.x;
    const int lid = tid & 31, wid = tid >> 5;
    const int wm = (wid & 1) * 64;      // warp m offset in tile
    const int wn = (wid >> 1) * 32;     // warp n offset in tile
    const int n0 = blockIdx.x * 128;
    const int m0 = blockIdx.y * 128;

    auto load_stage = [&](int buf, int k0) {
#pragma unroll
        for (int i = 0; i < 2; ++i) {
            int ch = tid + i * 256;               // 0..511
            int row = ch >> 2, c = ch & 3;
            uint32_t byte = (uint32_t)row * 64u + c * 16u;
            cpa16(smA + buf * STG + swz64(byte), A + (size_t)(m0 + row) * KA + k0 + c * 8);
        }
        const int kb = k0 & (KB - 1);
#pragma unroll
        for (int i = 0; i < 2; ++i) {
            int ch = tid + i * 256;
            int row = ch >> 2, c = ch & 3;
            uint32_t byte = (uint32_t)row * 64u + c * 16u;
            cpa16(smB + buf * STG + swz64(byte), Bw + (size_t)(n0 + row) * KB + kb + c * 8);
        }
        asm volatile("cp.async.commit_group;" ::: "memory");
    };

    float acc[4][4][4];
#pragma unroll
    for (int i = 0; i < 4; ++i)
#pragma unroll
        for (int j = 0; j < 4; ++j)
#pragma unroll
            for (int q = 0; q < 4; ++q) acc[i][j][q] = 0.f;

    for (int s = 0; s < GS - 1; ++s) load_stage(s, s * 32);

    for (int ks = 0; ks < nki; ++ks) {
        if (ks + GS - 2 < nki) asm volatile("cp.async.wait_group 2;" ::: "memory");
        else                   asm volatile("cp.async.wait_group 0;" ::: "memory");
        __syncthreads();
        const uint32_t sA = smA + (ks & (GS - 1)) * STG;
        const uint32_t sB = smB + (ks & (GS - 1)) * STG;
#pragma unroll
        for (int k2 = 0; k2 < 2; ++k2) {
            uint32_t af[4][4];
            uint32_t bfr[8];
#pragma unroll
            for (int tm = 0; tm < 4; ++tm) {
                int row = wm + tm * 16 + (lid & 15);
                uint32_t byte = (uint32_t)row * 64u + k2 * 32u + (lid >> 4) * 16u;
                ldsm4(af[tm], sA + swz64(byte));
            }
#pragma unroll
            for (int tn2 = 0; tn2 < 2; ++tn2) {
                int row = wn + tn2 * 16 + ((lid >> 4) << 3) + (lid & 7);
                uint32_t byte = (uint32_t)row * 64u + k2 * 32u + ((lid >> 3) & 1) * 16u;
                ldsm4(&bfr[tn2 * 4], sB + swz64(byte));
            }
#pragma unroll
            for (int tm = 0; tm < 4; ++tm)
#pragma unroll
                for (int tn = 0; tn < 4; ++tn)
                    mma_f16(acc[tm][tn], af[tm], &bfr[tn * 2]);
        }
        if (ks + GS - 1 < nki) load_stage((ks + GS - 1) & (GS - 1), (ks + GS - 1) * 32);
    }

    // epilogue
#pragma unroll
    for (int tm = 0; tm < 4; ++tm) {
        int r0 = m0 + wm + tm * 16 + (lid >> 2);
#pragma unroll
        for (int tn = 0; tn < 4; ++tn) {
            int c = n0 + wn + tn * 8 + (lid & 3) * 2;
            float2 bv = *(const float2*)(bias + c);
            float v00 = acc[tm][tn][0] + bv.x, v01 = acc[tm][tn][1] + bv.y;
            float v10 = acc[tm][tn][2] + bv.x, v11 = acc[tm][tn][3] + bv.y;
            if (sizeof(OutT) == 2) {
                __half2* p0 = (__half2*)((__half*)C + (size_t)r0 * N + c);
                __half2* p1 = (__half2*)((__half*)C + (size_t)(r0 + 8) * N + c);
                *p0 = __floats2half2_rn(v00, v01);
                *p1 = __floats2half2_rn(v10, v11);
            } else {
                *(float2*)((float*)C + (size_t)r0 * N + c) = make_float2(v00, v01);
                *(float2*)((float*)C + (size_t)(r0 + 8) * N + c) = make_float2(v10, v11);
            }
        }
    }
}

// ---------------------------------------------------------------------------
// Twiddle precompute (once per launch; exact same sincosf values)
// ---------------------------------------------------------------------------
__global__ __launch_bounds__(1024) void twiddle_kernel(float2* __restrict__ tw)
{
    const int j = blockIdx.x * 1024 + threadIdx.x;
    float sn, cs;
    sincosf((float)j * (-6.2831853071795864769f / (float)NFFT), &sn, &cs);
    tw[j] = make_float2(cs, sn);
}

// ---------------------------------------------------------------------------
// Conversion kernels
// ---------------------------------------------------------------------------
__device__ __forceinline__ void split_f16(float x, __half& hi, __half& lo) {
    hi = __float2half_rn(x);
    lo = __float2half_rn(x - __half2float(hi));
}

// x (M x 1024 fp32 row-major) -> A' (M x 2048 fp16 [hi, lo])
__global__ __launch_bounds__(256) void convert_a_kernel(
    const float* __restrict__ X, __half* __restrict__ Aout)
{
    const size_t idx = (size_t)blockIdx.x * 256 + threadIdx.x;
    const size_t m = idx >> 10;
    const int k = (int)(idx & 1023);
    float v = X[idx];
    __half hi, lo; split_f16(v, hi, lo);
    __half* row = Aout + m * KAUG;
    row[k] = hi; row[Dsz + k] = lo;
}

// W (1024 x N fp32) -> Bhi (N x 1024 fp16), transposed
__global__ __launch_bounds__(1024) void convert_b_kernel(
    const float* __restrict__ W, __half* __restrict__ Bout, const int N)
{
    __shared__ float sm[32][33];
    const int n0 = blockIdx.x * 32;
    const int k0 = blockIdx.y * 32;
    const int tx = threadIdx.x & 31, ty = threadIdx.x >> 5;
    sm[ty][tx] = W[(size_t)(k0 + ty) * N + n0 + tx];
    __syncthreads();
    const int n = n0 + ty, k = k0 + tx;
    Bout[(size_t)n * KB + k] = __float2half_rn(sm[tx][ty]);
}

// yT (B, D, L fp16) -> A2 (M=B*L x 1024 fp16), pure transpose (exact)
__global__ __launch_bounds__(1024) void convert_y_kernel(
    const __half* __restrict__ yT, __half* __restrict__ Aout)
{
    __shared__ float sm[32][33];
    const int t0 = blockIdx.x * 32;
    const int d0 = blockIdx.y * 32;
    const int b  = blockIdx.z;
    const int tx = threadIdx.x & 31, ty = threadIdx.x >> 5;
    sm[ty][tx] = __half2float(yT[((size_t)(b * Dsz + d0 + ty)) * Lsz + t0 + tx]);
    __syncthreads();
    const int t = t0 + ty, d = d0 + tx;
    Aout[((size_t)(b * Lsz + t)) * KB + d] = __float2half_rn(sm[tx][ty]);
}

// ---------------------------------------------------------------------------
// Short depthwise conv (k=3, causal) + gate; writes fp16 transposed (B, D, L)
// ---------------------------------------------------------------------------
__global__ __launch_bounds__(256) void shortconv_kernel(
    const __half* __restrict__ u, const float* __restrict__ sw,
    const float* __restrict__ sb, __half* __restrict__ x0T,
    __half* __restrict__ vgT)
{
    __shared__ float s[3][66 * 33];
    const int t0 = blockIdx.x * 64;
    const int d0 = blockIdx.y * 32;
    const int b  = blockIdx.z;
    const int tid = threadIdx.x;

#pragma unroll 1
    for (int c = 0; c < 3; ++c) {
        const __half* up = u + (size_t)b * Lsz * WIDTH + c * Dsz + d0;
        for (int idx = tid; idx < 66 * 32; idx += 256) {
            int row = idx >> 5;
            int dc  = idx & 31;
            int t   = t0 - 2 + row;
            float v = (t >= 0) ? __half2float(up[(size_t)t * WIDTH + dc]) : 0.0f;
            s[c][row * 33 + dc] = v;
        }
    }
    __syncthreads();

    for (int idx = tid; idx < 64 * 32; idx += 256) {
        int dc = idx >> 6;
        int tt = idx & 63;
        int d  = d0 + dc;
        int t  = t0 + tt;
        const float* w0 = sw + (size_t)d * 3;
        const float* w1 = sw + (size_t)(Dsz + d) * 3;
        const float* w2 = sw + (size_t)(2 * Dsz + d) * 3;
        float c0 = s[0][tt * 33 + dc] * w0[0] + s[0][(tt + 1) * 33 + dc] * w0[1]
                 + s[0][(tt + 2) * 33 + dc] * w0[2] + sb[d];
        float c1 = s[1][tt * 33 + dc] * w1[0] + s[1][(tt + 1) * 33 + dc] * w1[1]
                 + s[1][(tt + 2) * 33 + dc] * w1[2] + sb[Dsz + d];
        float c2 = s[2][tt * 33 + dc] * w2[0] + s[2][(tt + 1) * 33 + dc] * w2[1]
                 + s[2][(tt + 2) * 33 + dc] * w2[2] + sb[2 * Dsz + d];
        size_t o = ((size_t)(b * Dsz + d)) * Lsz + t;
        x0T[o] = __float2half_rn(c0);
        vgT[o] = __float2half_rn(c2 * c1);
    }
}

// ---------------------------------------------------------------------------
// Filter MLP: one block per position i; writes flipped+decayed kernel
// ---------------------------------------------------------------------------
__global__ __launch_bounds__(256) void filter_kernel(
    const float* __restrict__ W1, const float* __restrict__ b1,
    const float* __restrict__ f1, const float* __restrict__ W2,
    const float* __restrict__ b2, const float* __restrict__ f2,
    const float* __restrict__ W3, const float* __restrict__ b3,
    float* __restrict__ kkout)
{
    __shared__ float h1[64], h2[64];
    const int i = blockIdx.x;
    const int tid = threadIdx.x;
    const float tn = (float)i * (1.0f / 4095.0f);
    const float phase = 1e-4f * (6.2831853071795864769f * (float)i / 4096.0f);

    if (tid < 64) {
        float sp, cp; sincosf(phase, &sp, &cp);
        float a = tn * W1[tid] + cp * W1[64 + tid] - sp * W1[128 + tid] + b1[tid];
        h1[tid] = sinf(a * f1[tid]);
    }
    __syncthreads();
    if (tid < 64) {
        float a = b2[tid];
#pragma unroll 8
        for (int c = 0; c < 64; ++c) a += h1[c] * W2[c * 64 + tid];
        h2[tid] = sinf(a * f2[tid]);
    }
    __syncthreads();

    const float dmax = -15.350567286626971f;  // log(0.01)/0.3
    const float dmin = -3.0701134573253943f;  // log(0.01)/1.5
    const int row = Lsz - 1 - i;
    for (int d = tid; d < Dsz; d += 256) {
        float a = b3[d];
#pragma unroll 8
        for (int c = 0; c < 64; ++c) a += h2[c] * W3[c * Dsz + d];
        float delta = fabsf(dmax + (dmin - dmax) * ((float)d * (1.0f / 1023.0f)));
        kkout[(size_t)row * Dsz + d] = a * expf(-tn * delta);
    }
}

// ---------------------------------------------------------------------------
// Stockham FFT, N=8192: 6 radix-4 passes + 1 trivial radix-2.
// PADDED=true: input upper half implicitly zero (not written).
// ---------------------------------------------------------------------------
template<bool PADDED>
__device__ __forceinline__ float2* fft8192(float2* buf0, float2* buf1,
                                           const float2* __restrict__ tw,
                                           bool inverse)
{
    float2* src = buf0;
    float2* dst = buf1;
#pragma unroll 1
    for (int p = 0; p < 6; ++p) {
        const int s = 1 << (2 * p);
        __syncthreads();
        if (PADDED && p == 0) {
#pragma unroll
            for (int ii = 0; ii < NFFT / 4 / FFT_THREADS; ++ii) {
                const int i = threadIdx.x + ii * FFT_THREADS;
                float2 A = src[i];
                float2 C = src[i + 2048];
                float2 w1 = tw[i];
                float2 w2 = tw[2 * i];
                const float s1y = inverse ? -w1.y : w1.y;
                const float s2y = inverse ? -w2.y : w2.y;
                float2 jd = inverse ? make_float2(-C.y, C.x)
                                    : make_float2(C.y, -C.x);
                float2 t0 = make_float2(A.x + C.x, A.y + C.y);
                float2 t2 = make_float2(A.x - C.x, A.y - C.y);
                float2 t1 = make_float2(A.x + jd.x, A.y + jd.y);
                float2 t3 = make_float2(A.x - jd.x, A.y - jd.y);
                float2 o1 = make_float2(t1.x * w1.x - t1.y * s1y, t1.x * s1y + t1.y * w1.x);
                float2 o2 = make_float2(t2.x * w2.x - t2.y * s2y, t2.x * s2y + t2.y * w2.x);
                const float w3x = w1.x * w2.x - s1y * s2y;
                const float w3y = w1.x * s2y + s1y * w2.x;
                float2 o3 = make_float2(t3.x * w3x - t3.y * w3y, t3.x * w3y + t3.y * w3x);
                const int base = 4 * i;
                dst[base]     = t0;
                dst[base + 1] = o1;
                dst[base + 2] = o2;
                dst[base + 3] = o3;
            }
        } else {
#pragma unroll
            for (int ii = 0; ii < NFFT / 4 / FFT_THREADS; ++ii) {
                const int i = threadIdx.x + ii * FFT_THREADS;
                const int q = i & (s - 1);
                const int m = i - q;
                float2 A = src[i];
                float2 C = src[i + 2048];
                float2 B = src[i + 4096];
                float2 D = src[i + 6144];
                float2 w1 = tw[m];
                float2 w2 = tw[2 * m];
                const float s1y = inverse ? -w1.y : w1.y;
                const float s2y = inverse ? -w2.y : w2.y;
                float2 sAB = make_float2(A.x + B.x, A.y + B.y);
                float2 dAB = make_float2(A.x - B.x, A.y - B.y);
                float2 sCD = make_float2(C.x + D.x, C.y + D.y);
                float2 dCD = make_float2(C.x - D.x, C.y - D.y);
                float2 jd = inverse ? make_float2(-dCD.y, dCD.x)
                                    : make_float2(dCD.y, -dCD.x);
                float2 t0 = make_float2(sAB.x + sCD.x, sAB.y + sCD.y);
                float2 t2 = make_float2(sAB.x - sCD.x, sAB.y - sCD.y);
                float2 t1 = make_float2(dAB.x + jd.x, dAB.y + jd.y);
                float2 t3 = make_float2(dAB.x - jd.x, dAB.y - jd.y);
                float2 o1 = make_float2(t1.x * w1.x - t1.y * s1y, t1.x * s1y + t1.y * w1.x);
                float2 o2 = make_float2(t2.x * w2.x - t2.y * s2y, t2.x * s2y + t2.y * w2.x);
                const float w3x = w1.x * w2.x - s1y * s2y;
                const float w3y = w1.x * s2y + s1y * w2.x;
                float2 o3 = make_float2(t3.x * w3x - t3.y * w3y, t3.x * w3y + t3.y * w3x);
                const int base = 4 * m + q;
                dst[base]         = t0;
                dst[base + s]     = o1;
                dst[base + 2 * s] = o2;
                dst[base + 3 * s] = o3;
            }
        }
        float2* tmp = src; src = dst; dst = tmp;
    }
    // final radix-2 stage (s=4096): w = 1
    __syncthreads();
#pragma unroll
    for (int ii = 0; ii < NFFT / 2 / FFT_THREADS; ++ii) {
        const int t = threadIdx.x + ii * FFT_THREADS;
        float2 a = src[t];
        float2 b = src[t + 4096];
        dst[t]        = make_float2(a.x + b.x, a.y + b.y);
        dst[t + 4096] = make_float2(a.x - b.x, a.y - b.y);
    }
    __syncthreads();
    return dst;
}

__device__ __forceinline__ float2 cmulf(float2 a, float2 b) {
    return make_float2(a.x * b.x - a.y * b.y, a.x * b.y + a.y * b.x);
}

__global__ __launch_bounds__(FFT_THREADS) void kfft_kernel(
    const float* __restrict__ kk, const float2* __restrict__ twg,
    float2* __restrict__ Kf)
{
    extern __shared__ float2 sm[];
    float2* bufA = sm;
    float2* bufB = sm + NFFT;
    float2* tw   = sm + 2 * NFFT;
    const int d0 = blockIdx.x * 2;

    for (int j = threadIdx.x; j < NFFT / 2; j += FFT_THREADS) {
        tw[j] = twg[j];
        bufA[j] = make_float2(kk[(size_t)j * Dsz + d0], kk[(size_t)j * Dsz + d0 + 1]);
    }
    float2* Z = fft8192<true>(bufA, bufB, tw, false);
    float2* Ka = Kf + (size_t)d0 * 4097;
    float2* Kb = Ka + 4097;
    for (int k = threadIdx.x; k <= NFFT / 2; k += FFT_THREADS) {
        float2 z  = Z[k];
        float2 zc = Z[(NFFT - k) & (NFFT - 1)];
        Ka[k] = make_float2(0.5f * (z.x + zc.x), 0.5f * (z.y - zc.y));
        Kb[k] = make_float2(0.5f * (z.y + zc.y), 0.5f * (zc.x - z.x));
    }
}

__global__ __launch_bounds__(FFT_THREADS) void vfft_kernel(
    const __half* __restrict__ vgT, const __half* __restrict__ x0T,
    const float2* __restrict__ twg,
    const float2* __restrict__ Kf, const float* __restrict__ fbias,
    __half* __restrict__ yT)
{
    extern __shared__ float2 sm[];
    float2* bufA = sm;
    float2* bufB = sm + NFFT;
    float2* tw   = sm + 2 * NFFT;
    const int pair = blockIdx.x;
    const int b    = blockIdx.y;
    const int d0   = pair * 2;
    const __half* v0 = vgT + ((size_t)(b * Dsz + d0)) * Lsz;
    const __half* v1 = v0 + Lsz;

    for (int j = threadIdx.x; j < NFFT / 2; j += FFT_THREADS) {
        tw[j] = twg[j];
        bufA[j] = make_float2(__half2float(v0[j]), __half2float(v1[j]));
    }
    float2* Z = fft8192<true>(bufA, bufB, tw, false);   // == bufB
    float2* W = (Z == bufA) ? bufB : bufA;              // == bufA

    const float2* Ka = Kf + (size_t)d0 * 4097;
    const float2* Kb = Ka + 4097;
    for (int k = threadIdx.x; k <= NFFT / 2; k += FFT_THREADS) {
        float2 z  = Z[k];
        float2 zc = Z[(NFFT - k) & (NFFT - 1)];
        float2 Ak = make_float2(0.5f * (z.x + zc.x), 0.5f * (z.y - zc.y));
        float2 Bk = make_float2(0.5f * (z.y + zc.y), 0.5f * (zc.x - z.x));
        float2 Ya = cmulf(Ak, Ka[k]);
        float2 Yb = cmulf(Bk, Kb[k]);
        W[k] = make_float2(Ya.x - Yb.y, Ya.y + Yb.x);
        if (k != 0 && k != NFFT / 2)
            W[NFFT - k] = make_float2(Ya.x + Yb.y, Yb.x - Ya.y);
    }
    float2* res = fft8192<false>(W, Z, tw, true);       // unnormalized inverse

    const float invN = 1.0f / (float)NFFT;
    const float fb0 = fbias[d0], fb1 = fbias[d0 + 1];
    const __half* x0a = x0T + ((size_t)(b * Dsz + d0)) * Lsz;
    const __half* x0b = x0a + Lsz;
    __half* ya = yT + ((size_t)(b * Dsz + d0)) * Lsz;
    __half* yb = ya + Lsz;
    for (int t = threadIdx.x; t < Lsz; t += FFT_THREADS) {
        float2 w = res[t];
        ya[t] = __float2half_rn((w.x * invN + fb0) * __half2float(x0a[t]));
        yb[t] = __float2half_rn((w.y * invN + fb1) * __half2float(x0b[t]));
    }
}

// ---------------------------------------------------------------------------
// Launch
// ---------------------------------------------------------------------------
extern "C" void kernel_launch(void* const* d_in, const int* in_sizes, int n_in,
                              void* d_out, int out_size)
{
    const float* x       = (const float*)d_in[0];
    const float* W_in    = (const float*)d_in[1];
    const float* b_in    = (const float*)d_in[2];
    const float* short_w = (const float*)d_in[3];
    const float* short_b = (const float*)d_in[4];
    const float* W1      = (const float*)d_in[5];
    const float* b1      = (const float*)d_in[6];
    const float* f1      = (const float*)d_in[7];
    const float* W2      = (const float*)d_in[8];
    const float* b2      = (const float*)d_in[9];
    const float* f2      = (const float*)d_in[10];
    const float* W3      = (const float*)d_in[11];
    const float* b3      = (const float*)d_in[12];
    const float* fbias   = (const float*)d_in[13];
    const float* W_out   = (const float*)d_in[14];
    const float* b_out   = (const float*)d_in[15];
    float* out = (float*)d_out;

    float *p_kk;
    float2 *p_Kf, *p_tw;
    __half *p_u, *p_x0, *p_vg, *p_y, *p_A1, *p_Bt1, *p_A2, *p_Bt2;
    cudaGetSymbolAddress((void**)&p_u,   g_u);
    cudaGetSymbolAddress((void**)&p_x0,  g_x0T);
    cudaGetSymbolAddress((void**)&p_vg,  g_vgT);
    cudaGetSymbolAddress((void**)&p_kk,  g_kk);
    cudaGetSymbolAddress((void**)&p_Kf,  g_Kf);
    cudaGetSymbolAddress((void**)&p_y,   g_yT);
    cudaGetSymbolAddress((void**)&p_tw,  g_twg);
    cudaGetSymbolAddress((void**)&p_A1,  g_A1);
    cudaGetSymbolAddress((void**)&p_Bt1, g_Bt1);
    cudaGetSymbolAddress((void**)&p_A2,  g_A2);
    cudaGetSymbolAddress((void**)&p_Bt2, g_Bt2);

    cudaFuncSetAttribute(kfft_kernel, cudaFuncAttributeMaxDynamicSharedMemorySize,
                         FFT_SMEM_BYTES);
    cudaFuncSetAttribute(vfft_kernel, cudaFuncAttributeMaxDynamicSharedMemorySize,
                         FFT_SMEM_BYTES);
    cudaFuncSetAttribute(gemm_f16_kernel<__half>,
                         cudaFuncAttributeMaxDynamicSharedMemorySize, GM_SMEM);
    cudaFuncSetAttribute(gemm_f16_kernel<float>,
                         cudaFuncAttributeMaxDynamicSharedMemorySize, GM_SMEM);

    // 0) twiddle table
    twiddle_kernel<<<NFFT / 2 / 1024, 1024>>>(p_tw);

    // 1) operand conversion for GEMM1
    convert_a_kernel<<<(size_t)Msz * Dsz / 256, 256>>>(x, p_A1);
    convert_b_kernel<<<dim3(WIDTH / 32, Dsz / 32), 1024>>>(W_in, p_Bt1, WIDTH);

    // 2) u = x @ W_in + b_in  (fp16x2, K'=2048, fp16 output)
    gemm_f16_kernel<__half><<<dim3(WIDTH / 128, Msz / 128), 256, GM_SMEM>>>(
        p_A1, p_Bt1, b_in, p_u, Msz, WIDTH, KAUG, 64);

    // 3) short conv + gate -> x0T, vgT (fp16, transposed B,D,L)
    shortconv_kernel<<<dim3(Lsz / 64, Dsz / 32, Bsz), 256>>>(
        p_u, short_w, short_b, p_x0, p_vg);

    // 4) implicit filter (flipped + decayed)
    filter_kernel<<<Lsz, 256>>>(W1, b1, f1, W2, b2, f2, W3, b3, p_kk);

    // 5) filter spectra
    kfft_kernel<<<Dsz / 2, FFT_THREADS, FFT_SMEM_BYTES>>>(p_kk, p_tw, p_Kf);

    // 6) FFT conv + bias + x0 gate -> yT fp16
    vfft_kernel<<<dim3(Dsz / 2, Bsz), FFT_THREADS, FFT_SMEM_BYTES>>>(
        p_vg, p_x0, p_tw, p_Kf, fbias, p_y);

    // 7) operand conversion for GEMM2 (y transpose is exact fp16 copy)
    convert_b_kernel<<<dim3(Dsz / 32, Dsz / 32), 1024>>>(W_out, p_Bt2, Dsz);
    convert_y_kernel<<<dim3(Lsz / 32, Dsz / 32, Bsz), 1024>>>(p_y, p_A2);

    // 8) out = y @ W_out + b_out  (fp16, K=1024 — y already fp16, no split)
    gemm_f16_kernel<float><<<dim3(Dsz / 128, Msz / 128), 256, GM_SMEM>>>(
        p_A2, p_Bt2, b_out, out, Msz, Dsz, KB, 32);
}